// round 1
// baseline (speedup 1.0000x reference)
#include <cuda_runtime.h>
#include <math.h>

#define B_ 2
#define S_ 2048
#define D_ 1024
#define H_ 16
#define DH_ 64
#define M_ (B_ * S_)   // 4096 token rows

// -------- scratch (allocation-free: __device__ globals) --------
__device__ float g_q[M_ * D_];
__device__ float g_k[M_ * D_];
__device__ float g_v[M_ * D_];
__device__ float g_ctx[M_ * D_];
__device__ float g_gate[M_];

// ============================================================
// GEMM + bias: C[M,1024] = A[M,1024] @ W[1024,1024] + bias
// 64x64 tile, BK=16, 256 threads, 4x4 per-thread microtile.
// ============================================================
__global__ __launch_bounds__(256) void gemm_bias(const float* __restrict__ A,
                                                 const float* __restrict__ W,
                                                 const float* __restrict__ bias,
                                                 float* __restrict__ C)
{
    const int K = D_, N = D_;
    __shared__ float As[16][64];   // [k][m] (transposed for conflict-free a-frag reads)
    __shared__ float Bs[16][64];   // [k][n]

    int tid = threadIdx.x;
    int ty = tid >> 4;            // 0..15
    int tx = tid & 15;            // 0..15
    int m0 = blockIdx.y * 64;
    int n0 = blockIdx.x * 64;

    int arow = tid >> 2;          // 0..63
    int acol = (tid & 3) * 4;     // 0,4,8,12
    int brow = tid >> 4;          // 0..15
    int bcol = (tid & 15) * 4;    // 0..60

    float acc00=0,acc01=0,acc02=0,acc03=0;
    float acc10=0,acc11=0,acc12=0,acc13=0;
    float acc20=0,acc21=0,acc22=0,acc23=0;
    float acc30=0,acc31=0,acc32=0,acc33=0;

    for (int k0 = 0; k0 < K; k0 += 16) {
        float4 av = *(const float4*)&A[(size_t)(m0 + arow) * K + k0 + acol];
        float4 bv = *(const float4*)&W[(size_t)(k0 + brow) * N + n0 + bcol];
        As[acol + 0][arow] = av.x;
        As[acol + 1][arow] = av.y;
        As[acol + 2][arow] = av.z;
        As[acol + 3][arow] = av.w;
        *(float4*)&Bs[brow][bcol] = bv;
        __syncthreads();

        #pragma unroll
        for (int kk = 0; kk < 16; kk++) {
            float4 a4 = *(const float4*)&As[kk][ty * 4];
            float4 b4 = *(const float4*)&Bs[kk][tx * 4];
            acc00 += a4.x * b4.x; acc01 += a4.x * b4.y; acc02 += a4.x * b4.z; acc03 += a4.x * b4.w;
            acc10 += a4.y * b4.x; acc11 += a4.y * b4.y; acc12 += a4.y * b4.z; acc13 += a4.y * b4.w;
            acc20 += a4.z * b4.x; acc21 += a4.z * b4.y; acc22 += a4.z * b4.z; acc23 += a4.z * b4.w;
            acc30 += a4.w * b4.x; acc31 += a4.w * b4.y; acc32 += a4.w * b4.z; acc33 += a4.w * b4.w;
        }
        __syncthreads();
    }

    float4 bb = *(const float4*)&bias[n0 + tx * 4];
    {
        float4 o;
        o.x = acc00 + bb.x; o.y = acc01 + bb.y; o.z = acc02 + bb.z; o.w = acc03 + bb.w;
        *(float4*)&C[(size_t)(m0 + ty * 4 + 0) * N + n0 + tx * 4] = o;
        o.x = acc10 + bb.x; o.y = acc11 + bb.y; o.z = acc12 + bb.z; o.w = acc13 + bb.w;
        *(float4*)&C[(size_t)(m0 + ty * 4 + 1) * N + n0 + tx * 4] = o;
        o.x = acc20 + bb.x; o.y = acc21 + bb.y; o.z = acc22 + bb.z; o.w = acc23 + bb.w;
        *(float4*)&C[(size_t)(m0 + ty * 4 + 2) * N + n0 + tx * 4] = o;
        o.x = acc30 + bb.x; o.y = acc31 + bb.y; o.z = acc32 + bb.z; o.w = acc33 + bb.w;
        *(float4*)&C[(size_t)(m0 + ty * 4 + 3) * N + n0 + tx * 4] = o;
    }
}

// ============================================================
// Gating: gate[row] = sigmoid(gf * mean(hs[row,:]) + gb)
// ============================================================
__global__ __launch_bounds__(256) void gate_kernel(const float* __restrict__ hs,
                                                   const float* __restrict__ gf,
                                                   const float* __restrict__ gb,
                                                   float* __restrict__ gate)
{
    __shared__ float red[256];
    int row = blockIdx.x;
    const float* p = hs + (size_t)row * D_;
    float sum = 0.f;
    for (int i = threadIdx.x; i < D_; i += 256) sum += p[i];
    red[threadIdx.x] = sum;
    __syncthreads();
    #pragma unroll
    for (int st = 128; st > 0; st >>= 1) {
        if (threadIdx.x < st) red[threadIdx.x] += red[threadIdx.x + st];
        __syncthreads();
    }
    if (threadIdx.x == 0) {
        float mean = red[0] * (1.0f / D_);
        float z = gf[0] * mean + gb[0];
        gate[row] = 1.0f / (1.0f + expf(-z));
    }
}

// ============================================================
// Flash-style attention with post-softmax gating scalar.
// Block = 128 threads, each thread owns one query row of one (b,h).
// KC=8 keys per smem chunk (keeps unrolled body under I$ L1.5).
// ============================================================
#define KC_ 8

__global__ __launch_bounds__(128, 2) void attn_kernel(const float* __restrict__ q,
                                                      const float* __restrict__ k,
                                                      const float* __restrict__ v,
                                                      const float* __restrict__ gate,
                                                      float* __restrict__ ctx)
{
    __shared__ float4 Ks[KC_ * 16];   // KC_ keys x 64 floats
    __shared__ float4 Vs[KC_ * 16];

    int b = blockIdx.z;
    int h = blockIdx.y;
    int qi = blockIdx.x * 128 + threadIdx.x;

    const float4* qp = (const float4*)(q + ((size_t)(b * S_ + qi)) * D_ + h * DH_);
    float4 qr[16];
    #pragma unroll
    for (int i = 0; i < 16; i++) qr[i] = qp[i];

    float4 acc[16];
    #pragma unroll
    for (int i = 0; i < 16; i++) acc[i] = make_float4(0.f, 0.f, 0.f, 0.f);
    float mx = -1e30f;
    float l = 0.f;

    for (int kc = 0; kc < S_; kc += KC_) {
        // cooperative load: KC_*16 float4 over 128 threads (1 each)
        {
            int e = threadIdx.x;
            if (e < KC_ * 16) {
                int key = e >> 4;
                int f = e & 15;
                size_t off = ((size_t)(b * S_ + kc + key)) * D_ + h * DH_ + f * 4;
                Ks[e] = *(const float4*)(k + off);
                Vs[e] = *(const float4*)(v + off);
            }
        }
        __syncthreads();

        float s[KC_];
        #pragma unroll
        for (int j = 0; j < KC_; j++) {
            const float4* kr = &Ks[j * 16];
            float t0 = 0.f, t1 = 0.f, t2 = 0.f, t3 = 0.f;
            #pragma unroll
            for (int d = 0; d < 16; d++) {
                float4 kk = kr[d];
                t0 += qr[d].x * kk.x;
                t1 += qr[d].y * kk.y;
                t2 += qr[d].z * kk.z;
                t3 += qr[d].w * kk.w;
            }
            s[j] = ((t0 + t1) + (t2 + t3)) * 0.125f;   // 1/sqrt(64)
        }

        float mnew = mx;
        #pragma unroll
        for (int j = 0; j < KC_; j++) mnew = fmaxf(mnew, s[j]);

        float corr = expf(mx - mnew);
        float p[KC_];
        float ps = 0.f;
        #pragma unroll
        for (int j = 0; j < KC_; j++) { p[j] = expf(s[j] - mnew); ps += p[j]; }
        l = l * corr + ps;
        mx = mnew;

        #pragma unroll
        for (int i = 0; i < 16; i++) {
            acc[i].x *= corr; acc[i].y *= corr; acc[i].z *= corr; acc[i].w *= corr;
        }
        #pragma unroll
        for (int j = 0; j < KC_; j++) {
            const float4* vr = &Vs[j * 16];
            float pj = p[j];
            #pragma unroll
            for (int d = 0; d < 16; d++) {
                float4 vv = vr[d];
                acc[d].x += pj * vv.x;
                acc[d].y += pj * vv.y;
                acc[d].z += pj * vv.z;
                acc[d].w += pj * vv.w;
            }
        }
        __syncthreads();
    }

    float gsc = gate[b * S_ + qi] / l;   // gating scales probs => scales ctx
    float4* op = (float4*)(ctx + ((size_t)(b * S_ + qi)) * D_ + h * DH_);
    #pragma unroll
    for (int d = 0; d < 16; d++) {
        float4 o;
        o.x = acc[d].x * gsc;
        o.y = acc[d].y * gsc;
        o.z = acc[d].z * gsc;
        o.w = acc[d].w * gsc;
        op[d] = o;
    }
}

// ============================================================
// Launch
// ============================================================
extern "C" void kernel_launch(void* const* d_in, const int* in_sizes, int n_in,
                              void* d_out, int out_size)
{
    const float* hs = (const float*)d_in[0];
    const float* Wq = (const float*)d_in[1];
    const float* bq = (const float*)d_in[2];
    const float* Wk = (const float*)d_in[3];
    const float* bk = (const float*)d_in[4];
    const float* Wv = (const float*)d_in[5];
    const float* bv = (const float*)d_in[6];
    const float* Wo = (const float*)d_in[7];
    const float* bo = (const float*)d_in[8];
    const float* gf = (const float*)d_in[9];
    const float* gb = (const float*)d_in[10];
    float* out = (float*)d_out;

    float *qp, *kp, *vp, *cp, *gp;
    cudaGetSymbolAddress((void**)&qp, g_q);
    cudaGetSymbolAddress((void**)&kp, g_k);
    cudaGetSymbolAddress((void**)&vp, g_v);
    cudaGetSymbolAddress((void**)&cp, g_ctx);
    cudaGetSymbolAddress((void**)&gp, g_gate);

    dim3 gg(D_ / 64, M_ / 64);   // 16 x 64 blocks

    gemm_bias<<<gg, 256>>>(hs, Wq, bq, qp);
    gemm_bias<<<gg, 256>>>(hs, Wk, bk, kp);
    gemm_bias<<<gg, 256>>>(hs, Wv, bv, vp);
    gate_kernel<<<M_, 256>>>(hs, gf, gb, gp);
    attn_kernel<<<dim3(S_ / 128, H_, B_), 128>>>(qp, kp, vp, gp, cp);
    gemm_bias<<<gg, 256>>>(cp, Wo, bo, out);
}

// round 2
// speedup vs baseline: 1.3048x; 1.3048x over previous
#include <cuda_runtime.h>
#include <math.h>
#include <stdint.h>

#define B_ 2
#define S_ 2048
#define D_ 1024
#define H_ 16
#define DH_ 64
#define M_ (B_ * S_)   // 4096 token rows

// -------- scratch (allocation-free: __device__ globals) --------
__device__ float g_q[M_ * D_];
__device__ float g_k[M_ * D_];
__device__ float g_v[M_ * D_];
__device__ float g_ctx[M_ * D_];
__device__ float g_gate[M_];

// ============================================================
// tf32 helpers
// ============================================================
__device__ __forceinline__ float tf32r(float x) {
    uint32_t u;
    asm("cvt.rna.tf32.f32 %0, %1;" : "=r"(u) : "f"(x));
    return __uint_as_float(u);
}

__device__ __forceinline__ void mma_tf32(float4& d, const uint32_t a[4], const uint32_t b[2]) {
    asm volatile(
        "mma.sync.aligned.m16n8k8.row.col.f32.tf32.tf32.f32 "
        "{%0,%1,%2,%3}, {%4,%5,%6,%7}, {%8,%9}, {%0,%1,%2,%3};"
        : "+f"(d.x), "+f"(d.y), "+f"(d.z), "+f"(d.w)
        : "r"(a[0]), "r"(a[1]), "r"(a[2]), "r"(a[3]), "r"(b[0]), "r"(b[1]));
}

// ============================================================
// tf32 tensor-core GEMM + bias:
// C[M,1024] = A[M,1024] @ W[1024,1024] + bias
// 128x128 tile, BK=32, 256 threads = 8 warps (2x4), 64x32 per warp.
// ============================================================
__global__ __launch_bounds__(256, 2) void gemm_tf32(const float* __restrict__ A,
                                                    const float* __restrict__ W,
                                                    const float* __restrict__ bias,
                                                    float* __restrict__ C)
{
    __shared__ float As[128][36];    // [m][k], stride 36 -> conflict-free A-frag LDS
    __shared__ float Bs[32][136];    // [k][n], stride 136 -> conflict-free B-frag LDS

    const int tid  = threadIdx.x;
    const int lane = tid & 31;
    const int warp = tid >> 5;
    const int wm = warp & 1;         // 0..1  (64 rows each)
    const int wn = warp >> 1;        // 0..3  (32 cols each)
    const int g  = lane >> 2;        // group 0..7
    const int t4 = lane & 3;         // 0..3

    const int m0 = blockIdx.y * 128;
    const int n0 = blockIdx.x * 128;

    // global load assignments
    const int ar = tid >> 1;                // 0..127 (A row)
    const int ak = (tid & 1) * 16;          // A k offset
    const int br = tid >> 3;                // 0..31  (B k row)
    const int bc = (tid & 7) * 16;          // B col offset

    float4 acc[4][4];
    #pragma unroll
    for (int mt = 0; mt < 4; mt++)
        #pragma unroll
        for (int nt = 0; nt < 4; nt++)
            acc[mt][nt] = make_float4(0.f, 0.f, 0.f, 0.f);

    for (int k0 = 0; k0 < D_; k0 += 32) {
        // ---- load A tile 128x32 (cvt to tf32 inline) ----
        #pragma unroll
        for (int i = 0; i < 4; i++) {
            float4 v = *(const float4*)&A[(size_t)(m0 + ar) * D_ + k0 + ak + i * 4];
            v.x = tf32r(v.x); v.y = tf32r(v.y); v.z = tf32r(v.z); v.w = tf32r(v.w);
            *(float4*)&As[ar][ak + i * 4] = v;
        }
        // ---- load B tile 32x128 ----
        #pragma unroll
        for (int i = 0; i < 4; i++) {
            float4 v = *(const float4*)&W[(size_t)(k0 + br) * D_ + n0 + bc + i * 4];
            v.x = tf32r(v.x); v.y = tf32r(v.y); v.z = tf32r(v.z); v.w = tf32r(v.w);
            *(float4*)&Bs[br][bc + i * 4] = v;
        }
        __syncthreads();

        #pragma unroll
        for (int ks = 0; ks < 4; ks++) {
            const int kb = ks * 8;
            uint32_t af[4][4];
            uint32_t bf[4][2];
            #pragma unroll
            for (int mt = 0; mt < 4; mt++) {
                int row = wm * 64 + mt * 16 + g;
                af[mt][0] = __float_as_uint(As[row][kb + t4]);
                af[mt][1] = __float_as_uint(As[row + 8][kb + t4]);
                af[mt][2] = __float_as_uint(As[row][kb + t4 + 4]);
                af[mt][3] = __float_as_uint(As[row + 8][kb + t4 + 4]);
            }
            #pragma unroll
            for (int nt = 0; nt < 4; nt++) {
                int col = wn * 32 + nt * 8 + g;
                bf[nt][0] = __float_as_uint(Bs[kb + t4][col]);
                bf[nt][1] = __float_as_uint(Bs[kb + t4 + 4][col]);
            }
            #pragma unroll
            for (int mt = 0; mt < 4; mt++)
                #pragma unroll
                for (int nt = 0; nt < 4; nt++)
                    mma_tf32(acc[mt][nt], af[mt], bf[nt]);
        }
        __syncthreads();
    }

    // ---- epilogue: bias + store ----
    #pragma unroll
    for (int nt = 0; nt < 4; nt++) {
        int col = n0 + wn * 32 + nt * 8 + t4 * 2;
        float2 bb = *(const float2*)&bias[col];
        #pragma unroll
        for (int mt = 0; mt < 4; mt++) {
            int row = m0 + wm * 64 + mt * 16 + g;
            float2 o;
            o.x = acc[mt][nt].x + bb.x;
            o.y = acc[mt][nt].y + bb.y;
            *(float2*)&C[(size_t)row * D_ + col] = o;
            o.x = acc[mt][nt].z + bb.x;
            o.y = acc[mt][nt].w + bb.y;
            *(float2*)&C[(size_t)(row + 8) * D_ + col] = o;
        }
    }
}

// ============================================================
// Gating: gate[row] = sigmoid(gf * mean(hs[row,:]) + gb)
// ============================================================
__global__ __launch_bounds__(256) void gate_kernel(const float* __restrict__ hs,
                                                   const float* __restrict__ gf,
                                                   const float* __restrict__ gb,
                                                   float* __restrict__ gate)
{
    __shared__ float red[256];
    int row = blockIdx.x;
    const float* p = hs + (size_t)row * D_;
    float sum = 0.f;
    for (int i = threadIdx.x; i < D_; i += 256) sum += p[i];
    red[threadIdx.x] = sum;
    __syncthreads();
    #pragma unroll
    for (int st = 128; st > 0; st >>= 1) {
        if (threadIdx.x < st) red[threadIdx.x] += red[threadIdx.x + st];
        __syncthreads();
    }
    if (threadIdx.x == 0) {
        float mean = red[0] * (1.0f / D_);
        float z = gf[0] * mean + gb[0];
        gate[row] = 1.0f / (1.0f + expf(-z));
    }
}

// ============================================================
// Flash-style attention with post-softmax gating scalar.
// Block = 128 threads, each thread owns one query row of one (b,h).
// ============================================================
#define KC_ 8

__global__ __launch_bounds__(128, 2) void attn_kernel(const float* __restrict__ q,
                                                      const float* __restrict__ k,
                                                      const float* __restrict__ v,
                                                      const float* __restrict__ gate,
                                                      float* __restrict__ ctx)
{
    __shared__ float4 Ks[KC_ * 16];
    __shared__ float4 Vs[KC_ * 16];

    int b = blockIdx.z;
    int h = blockIdx.y;
    int qi = blockIdx.x * 128 + threadIdx.x;

    const float4* qp = (const float4*)(q + ((size_t)(b * S_ + qi)) * D_ + h * DH_);
    float4 qr[16];
    #pragma unroll
    for (int i = 0; i < 16; i++) qr[i] = qp[i];

    float4 acc[16];
    #pragma unroll
    for (int i = 0; i < 16; i++) acc[i] = make_float4(0.f, 0.f, 0.f, 0.f);
    float mx = -1e30f;
    float l = 0.f;

    for (int kc = 0; kc < S_; kc += KC_) {
        {
            int e = threadIdx.x;
            if (e < KC_ * 16) {
                int key = e >> 4;
                int f = e & 15;
                size_t off = ((size_t)(b * S_ + kc + key)) * D_ + h * DH_ + f * 4;
                Ks[e] = *(const float4*)(k + off);
                Vs[e] = *(const float4*)(v + off);
            }
        }
        __syncthreads();

        float s[KC_];
        #pragma unroll
        for (int j = 0; j < KC_; j++) {
            const float4* kr = &Ks[j * 16];
            float t0 = 0.f, t1 = 0.f, t2 = 0.f, t3 = 0.f;
            #pragma unroll
            for (int d = 0; d < 16; d++) {
                float4 kk = kr[d];
                t0 += qr[d].x * kk.x;
                t1 += qr[d].y * kk.y;
                t2 += qr[d].z * kk.z;
                t3 += qr[d].w * kk.w;
            }
            s[j] = ((t0 + t1) + (t2 + t3)) * 0.125f;
        }

        float mnew = mx;
        #pragma unroll
        for (int j = 0; j < KC_; j++) mnew = fmaxf(mnew, s[j]);

        float corr = expf(mx - mnew);
        float p[KC_];
        float ps = 0.f;
        #pragma unroll
        for (int j = 0; j < KC_; j++) { p[j] = expf(s[j] - mnew); ps += p[j]; }
        l = l * corr + ps;
        mx = mnew;

        #pragma unroll
        for (int i = 0; i < 16; i++) {
            acc[i].x *= corr; acc[i].y *= corr; acc[i].z *= corr; acc[i].w *= corr;
        }
        #pragma unroll
        for (int j = 0; j < KC_; j++) {
            const float4* vr = &Vs[j * 16];
            float pj = p[j];
            #pragma unroll
            for (int d = 0; d < 16; d++) {
                float4 vv = vr[d];
                acc[d].x += pj * vv.x;
                acc[d].y += pj * vv.y;
                acc[d].z += pj * vv.z;
                acc[d].w += pj * vv.w;
            }
        }
        __syncthreads();
    }

    float gsc = gate[b * S_ + qi] / l;
    float4* op = (float4*)(ctx + ((size_t)(b * S_ + qi)) * D_ + h * DH_);
    #pragma unroll
    for (int d = 0; d < 16; d++) {
        float4 o;
        o.x = acc[d].x * gsc;
        o.y = acc[d].y * gsc;
        o.z = acc[d].z * gsc;
        o.w = acc[d].w * gsc;
        op[d] = o;
    }
}

// ============================================================
// Launch
// ============================================================
extern "C" void kernel_launch(void* const* d_in, const int* in_sizes, int n_in,
                              void* d_out, int out_size)
{
    const float* hs = (const float*)d_in[0];
    const float* Wq = (const float*)d_in[1];
    const float* bq = (const float*)d_in[2];
    const float* Wk = (const float*)d_in[3];
    const float* bk = (const float*)d_in[4];
    const float* Wv = (const float*)d_in[5];
    const float* bv = (const float*)d_in[6];
    const float* Wo = (const float*)d_in[7];
    const float* bo = (const float*)d_in[8];
    const float* gf = (const float*)d_in[9];
    const float* gb = (const float*)d_in[10];
    float* out = (float*)d_out;

    float *qp, *kp, *vp, *cp, *gp;
    cudaGetSymbolAddress((void**)&qp, g_q);
    cudaGetSymbolAddress((void**)&kp, g_k);
    cudaGetSymbolAddress((void**)&vp, g_v);
    cudaGetSymbolAddress((void**)&cp, g_ctx);
    cudaGetSymbolAddress((void**)&gp, g_gate);

    dim3 gg(D_ / 128, M_ / 128);   // 8 x 32 = 256 blocks

    gemm_tf32<<<gg, 256>>>(hs, Wq, bq, qp);
    gemm_tf32<<<gg, 256>>>(hs, Wk, bk, kp);
    gemm_tf32<<<gg, 256>>>(hs, Wv, bv, vp);
    gate_kernel<<<M_, 256>>>(hs, gf, gb, gp);
    attn_kernel<<<dim3(S_ / 128, H_, B_), 128>>>(qp, kp, vp, gp, cp);
    gemm_tf32<<<gg, 256>>>(cp, Wo, bo, out);
}

// round 3
// speedup vs baseline: 3.2511x; 2.4917x over previous
#include <cuda_runtime.h>
#include <math.h>
#include <stdint.h>

#define B_ 2
#define S_ 2048
#define D_ 1024
#define H_ 16
#define DH_ 64
#define M_ (B_ * S_)   // 4096 token rows

// -------- scratch (allocation-free: __device__ globals) --------
__device__ float g_q[M_ * D_];
__device__ float g_k[M_ * D_];
__device__ float g_v[M_ * D_];
__device__ float g_ctx[M_ * D_];
__device__ float g_gate[M_];

// ============================================================
// tf32 helpers
// ============================================================
__device__ __forceinline__ float tf32r(float x) {
    uint32_t u;
    asm("cvt.rna.tf32.f32 %0, %1;" : "=r"(u) : "f"(x));
    return __uint_as_float(u);
}
__device__ __forceinline__ uint32_t tf32u(float x) {
    uint32_t u;
    asm("cvt.rna.tf32.f32 %0, %1;" : "=r"(u) : "f"(x));
    return u;
}

__device__ __forceinline__ void mma_tf32(float4& d, const uint32_t a[4], uint32_t b0, uint32_t b1) {
    asm volatile(
        "mma.sync.aligned.m16n8k8.row.col.f32.tf32.tf32.f32 "
        "{%0,%1,%2,%3}, {%4,%5,%6,%7}, {%8,%9}, {%0,%1,%2,%3};"
        : "+f"(d.x), "+f"(d.y), "+f"(d.z), "+f"(d.w)
        : "r"(a[0]), "r"(a[1]), "r"(a[2]), "r"(a[3]), "r"(b0), "r"(b1));
}

// ============================================================
// tf32 tensor-core GEMM + bias (unchanged from R2)
// ============================================================
__global__ __launch_bounds__(256, 2) void gemm_tf32(const float* __restrict__ A,
                                                    const float* __restrict__ W,
                                                    const float* __restrict__ bias,
                                                    float* __restrict__ C)
{
    __shared__ float As[128][36];
    __shared__ float Bs[32][136];

    const int tid  = threadIdx.x;
    const int lane = tid & 31;
    const int warp = tid >> 5;
    const int wm = warp & 1;
    const int wn = warp >> 1;
    const int g  = lane >> 2;
    const int t4 = lane & 3;

    const int m0 = blockIdx.y * 128;
    const int n0 = blockIdx.x * 128;

    const int ar = tid >> 1;
    const int ak = (tid & 1) * 16;
    const int br = tid >> 3;
    const int bc = (tid & 7) * 16;

    float4 acc[4][4];
    #pragma unroll
    for (int mt = 0; mt < 4; mt++)
        #pragma unroll
        for (int nt = 0; nt < 4; nt++)
            acc[mt][nt] = make_float4(0.f, 0.f, 0.f, 0.f);

    for (int k0 = 0; k0 < D_; k0 += 32) {
        #pragma unroll
        for (int i = 0; i < 4; i++) {
            float4 v = *(const float4*)&A[(size_t)(m0 + ar) * D_ + k0 + ak + i * 4];
            v.x = tf32r(v.x); v.y = tf32r(v.y); v.z = tf32r(v.z); v.w = tf32r(v.w);
            *(float4*)&As[ar][ak + i * 4] = v;
        }
        #pragma unroll
        for (int i = 0; i < 4; i++) {
            float4 v = *(const float4*)&W[(size_t)(k0 + br) * D_ + n0 + bc + i * 4];
            v.x = tf32r(v.x); v.y = tf32r(v.y); v.z = tf32r(v.z); v.w = tf32r(v.w);
            *(float4*)&Bs[br][bc + i * 4] = v;
        }
        __syncthreads();

        #pragma unroll
        for (int ks = 0; ks < 4; ks++) {
            const int kb = ks * 8;
            uint32_t af[4][4];
            uint32_t bf[4][2];
            #pragma unroll
            for (int mt = 0; mt < 4; mt++) {
                int row = wm * 64 + mt * 16 + g;
                af[mt][0] = __float_as_uint(As[row][kb + t4]);
                af[mt][1] = __float_as_uint(As[row + 8][kb + t4]);
                af[mt][2] = __float_as_uint(As[row][kb + t4 + 4]);
                af[mt][3] = __float_as_uint(As[row + 8][kb + t4 + 4]);
            }
            #pragma unroll
            for (int nt = 0; nt < 4; nt++) {
                int col = wn * 32 + nt * 8 + g;
                bf[nt][0] = __float_as_uint(Bs[kb + t4][col]);
                bf[nt][1] = __float_as_uint(Bs[kb + t4 + 4][col]);
            }
            #pragma unroll
            for (int mt = 0; mt < 4; mt++)
                #pragma unroll
                for (int nt = 0; nt < 4; nt++)
                    mma_tf32(acc[mt][nt], af[mt], bf[nt][0], bf[nt][1]);
        }
        __syncthreads();
    }

    #pragma unroll
    for (int nt = 0; nt < 4; nt++) {
        int col = n0 + wn * 32 + nt * 8 + t4 * 2;
        float2 bb = *(const float2*)&bias[col];
        #pragma unroll
        for (int mt = 0; mt < 4; mt++) {
            int row = m0 + wm * 64 + mt * 16 + g;
            float2 o;
            o.x = acc[mt][nt].x + bb.x;
            o.y = acc[mt][nt].y + bb.y;
            *(float2*)&C[(size_t)row * D_ + col] = o;
            o.x = acc[mt][nt].z + bb.x;
            o.y = acc[mt][nt].w + bb.y;
            *(float2*)&C[(size_t)(row + 8) * D_ + col] = o;
        }
    }
}

// ============================================================
// Gating: gate[row] = sigmoid(gf * mean(hs[row,:]) + gb)
// ============================================================
__global__ __launch_bounds__(256) void gate_kernel(const float* __restrict__ hs,
                                                   const float* __restrict__ gf,
                                                   const float* __restrict__ gb,
                                                   float* __restrict__ gate)
{
    __shared__ float red[256];
    int row = blockIdx.x;
    const float* p = hs + (size_t)row * D_;
    float sum = 0.f;
    for (int i = threadIdx.x; i < D_; i += 256) sum += p[i];
    red[threadIdx.x] = sum;
    __syncthreads();
    #pragma unroll
    for (int st = 128; st > 0; st >>= 1) {
        if (threadIdx.x < st) red[threadIdx.x] += red[threadIdx.x + st];
        __syncthreads();
    }
    if (threadIdx.x == 0) {
        float mean = red[0] * (1.0f / D_);
        float z = gf[0] * mean + gb[0];
        gate[row] = 1.0f / (1.0f + expf(-z));
    }
}

// ============================================================
// Tensor-core flash attention (tf32 m16n8k8) + post-softmax gate.
// Block = 128 thr (4 warps) = 64-query tile of one (b,h).
// Key chunks of 64. K smem tile aliased by P after QK^T.
// ============================================================
#define SC_ (0.125f * 1.44269504f)   // 1/sqrt(64) * log2(e)

__global__ __launch_bounds__(128) void attn_mma(const float* __restrict__ q,
                                                const float* __restrict__ k,
                                                const float* __restrict__ v,
                                                const float* __restrict__ gate,
                                                float* __restrict__ ctx)
{
    __shared__ float KP[64][68];   // K tile (QK phase) then P tile (PV phase)
    __shared__ float Vs[64][72];   // V tile

    const int b  = blockIdx.z;
    const int h  = blockIdx.y;
    const int q0 = blockIdx.x * 64;
    const int tid  = threadIdx.x;
    const int lane = tid & 31;
    const int w    = tid >> 5;
    const int g  = lane >> 2;
    const int t4 = lane & 3;
    const int wrow = w * 16;

    // ---- stage Q tile through KP, pull fragments to registers ----
    #pragma unroll
    for (int i = 0; i < 8; i++) {
        int e = tid + i * 128;       // 0..1023
        int row = e >> 4, f = e & 15;
        float4 val = *(const float4*)(q + ((size_t)(b * S_ + q0 + row)) * D_ + h * DH_ + f * 4);
        val.x = tf32r(val.x); val.y = tf32r(val.y); val.z = tf32r(val.z); val.w = tf32r(val.w);
        *(float4*)&KP[row][f * 4] = val;
    }
    __syncthreads();
    uint32_t aq[8][4];
    #pragma unroll
    for (int ks = 0; ks < 8; ks++) {
        int kb = ks * 8;
        aq[ks][0] = __float_as_uint(KP[wrow + g][kb + t4]);
        aq[ks][1] = __float_as_uint(KP[wrow + 8 + g][kb + t4]);
        aq[ks][2] = __float_as_uint(KP[wrow + g][kb + t4 + 4]);
        aq[ks][3] = __float_as_uint(KP[wrow + 8 + g][kb + t4 + 4]);
    }
    __syncthreads();

    float4 accO[8];
    #pragma unroll
    for (int nt = 0; nt < 8; nt++) accO[nt] = make_float4(0.f, 0.f, 0.f, 0.f);
    float mxlo = -1e30f, mxhi = -1e30f, llo = 0.f, lhi = 0.f;

    for (int kc = 0; kc < S_; kc += 64) {
        // ---- load K chunk -> KP, V chunk -> Vs ----
        #pragma unroll
        for (int i = 0; i < 8; i++) {
            int e = tid + i * 128;
            int row = e >> 4, f = e & 15;
            size_t off = ((size_t)(b * S_ + kc + row)) * D_ + h * DH_ + f * 4;
            float4 kv = *(const float4*)(k + off);
            kv.x = tf32r(kv.x); kv.y = tf32r(kv.y); kv.z = tf32r(kv.z); kv.w = tf32r(kv.w);
            *(float4*)&KP[row][f * 4] = kv;
            float4 vv = *(const float4*)(v + off);
            vv.x = tf32r(vv.x); vv.y = tf32r(vv.y); vv.z = tf32r(vv.z); vv.w = tf32r(vv.w);
            *(float4*)&Vs[row][f * 4] = vv;
        }
        __syncthreads();

        // ---- scores = Q @ K^T  (16 rows x 64 keys per warp) ----
        float4 s[8];
        #pragma unroll
        for (int nt = 0; nt < 8; nt++) {
            float4 acc = make_float4(0.f, 0.f, 0.f, 0.f);
            #pragma unroll
            for (int ks = 0; ks < 8; ks++) {
                int kb = ks * 8;
                uint32_t b0 = __float_as_uint(KP[nt * 8 + g][kb + t4]);
                uint32_t b1 = __float_as_uint(KP[nt * 8 + g][kb + t4 + 4]);
                mma_tf32(acc, aq[ks], b0, b1);
            }
            s[nt] = acc;
        }
        __syncthreads();   // everyone done reading K before P aliases KP

        // ---- online softmax (rows g and g+8) ----
        float mlo = -1e30f, mhi = -1e30f;
        #pragma unroll
        for (int nt = 0; nt < 8; nt++) {
            mlo = fmaxf(mlo, fmaxf(s[nt].x, s[nt].y));
            mhi = fmaxf(mhi, fmaxf(s[nt].z, s[nt].w));
        }
        mlo = fmaxf(mlo, __shfl_xor_sync(0xffffffffu, mlo, 1));
        mlo = fmaxf(mlo, __shfl_xor_sync(0xffffffffu, mlo, 2));
        mhi = fmaxf(mhi, __shfl_xor_sync(0xffffffffu, mhi, 1));
        mhi = fmaxf(mhi, __shfl_xor_sync(0xffffffffu, mhi, 2));

        float mnlo = fmaxf(mxlo, mlo);
        float mnhi = fmaxf(mxhi, mhi);
        float clo = exp2f((mxlo - mnlo) * SC_);
        float chi = exp2f((mxhi - mnhi) * SC_);

        float slo = 0.f, shi = 0.f;
        #pragma unroll
        for (int nt = 0; nt < 8; nt++) {
            s[nt].x = exp2f((s[nt].x - mnlo) * SC_);
            s[nt].y = exp2f((s[nt].y - mnlo) * SC_);
            s[nt].z = exp2f((s[nt].z - mnhi) * SC_);
            s[nt].w = exp2f((s[nt].w - mnhi) * SC_);
            slo += s[nt].x + s[nt].y;
            shi += s[nt].z + s[nt].w;
        }
        slo += __shfl_xor_sync(0xffffffffu, slo, 1);
        slo += __shfl_xor_sync(0xffffffffu, slo, 2);
        shi += __shfl_xor_sync(0xffffffffu, shi, 1);
        shi += __shfl_xor_sync(0xffffffffu, shi, 2);
        llo = llo * clo + slo;
        lhi = lhi * chi + shi;
        mxlo = mnlo; mxhi = mnhi;

        #pragma unroll
        for (int nt = 0; nt < 8; nt++) {
            accO[nt].x *= clo; accO[nt].y *= clo;
            accO[nt].z *= chi; accO[nt].w *= chi;
        }

        // ---- store P (tf32) to warp-private region of KP ----
        #pragma unroll
        for (int nt = 0; nt < 8; nt++) {
            int col = nt * 8 + 2 * t4;
            KP[wrow + g][col]     = __uint_as_float(tf32u(s[nt].x));
            KP[wrow + g][col + 1] = __uint_as_float(tf32u(s[nt].y));
            KP[wrow + 8 + g][col]     = __uint_as_float(tf32u(s[nt].z));
            KP[wrow + 8 + g][col + 1] = __uint_as_float(tf32u(s[nt].w));
        }
        __syncwarp();

        // ---- O += P @ V ----
        #pragma unroll
        for (int ks = 0; ks < 8; ks++) {
            int kb = ks * 8;
            uint32_t ap[4];
            ap[0] = __float_as_uint(KP[wrow + g][kb + t4]);
            ap[1] = __float_as_uint(KP[wrow + 8 + g][kb + t4]);
            ap[2] = __float_as_uint(KP[wrow + g][kb + t4 + 4]);
            ap[3] = __float_as_uint(KP[wrow + 8 + g][kb + t4 + 4]);
            #pragma unroll
            for (int nt = 0; nt < 8; nt++) {
                uint32_t b0 = __float_as_uint(Vs[kb + t4][nt * 8 + g]);
                uint32_t b1 = __float_as_uint(Vs[kb + t4 + 4][nt * 8 + g]);
                mma_tf32(accO[nt], ap, b0, b1);
            }
        }
        __syncthreads();   // all reads of KP/Vs done before next chunk's stores
    }

    // ---- epilogue: gate/l scale, store ctx ----
    int qlo = q0 + wrow + g;
    int qhi = qlo + 8;
    float glo = gate[b * S_ + qlo] / llo;
    float ghi = gate[b * S_ + qhi] / lhi;
    #pragma unroll
    for (int nt = 0; nt < 8; nt++) {
        int col = h * DH_ + nt * 8 + 2 * t4;
        float2 o1; o1.x = accO[nt].x * glo; o1.y = accO[nt].y * glo;
        *(float2*)&ctx[((size_t)(b * S_ + qlo)) * D_ + col] = o1;
        float2 o2; o2.x = accO[nt].z * ghi; o2.y = accO[nt].w * ghi;
        *(float2*)&ctx[((size_t)(b * S_ + qhi)) * D_ + col] = o2;
    }
}

// ============================================================
// Launch
// ============================================================
extern "C" void kernel_launch(void* const* d_in, const int* in_sizes, int n_in,
                              void* d_out, int out_size)
{
    const float* hs = (const float*)d_in[0];
    const float* Wq = (const float*)d_in[1];
    const float* bq = (const float*)d_in[2];
    const float* Wk = (const float*)d_in[3];
    const float* bk = (const float*)d_in[4];
    const float* Wv = (const float*)d_in[5];
    const float* bv = (const float*)d_in[6];
    const float* Wo = (const float*)d_in[7];
    const float* bo = (const float*)d_in[8];
    const float* gf = (const float*)d_in[9];
    const float* gb = (const float*)d_in[10];
    float* out = (float*)d_out;

    float *qp, *kp, *vp, *cp, *gp;
    cudaGetSymbolAddress((void**)&qp, g_q);
    cudaGetSymbolAddress((void**)&kp, g_k);
    cudaGetSymbolAddress((void**)&vp, g_v);
    cudaGetSymbolAddress((void**)&cp, g_ctx);
    cudaGetSymbolAddress((void**)&gp, g_gate);

    dim3 gg(D_ / 128, M_ / 128);   // 8 x 32 = 256 blocks

    gemm_tf32<<<gg, 256>>>(hs, Wq, bq, qp);
    gemm_tf32<<<gg, 256>>>(hs, Wk, bk, kp);
    gemm_tf32<<<gg, 256>>>(hs, Wv, bv, vp);
    gate_kernel<<<M_, 256>>>(hs, gf, gb, gp);
    attn_mma<<<dim3(S_ / 64, H_, B_), 128>>>(qp, kp, vp, gp, cp);
    gemm_tf32<<<gg, 256>>>(cp, Wo, bo, out);
}

// round 4
// speedup vs baseline: 3.6289x; 1.1162x over previous
#include <cuda_runtime.h>
#include <math.h>
#include <stdint.h>

#define B_ 2
#define S_ 2048
#define D_ 1024
#define H_ 16
#define DH_ 64
#define M_ (B_ * S_)   // 4096 token rows

// -------- scratch (allocation-free: __device__ globals) --------
__device__ float g_q[M_ * D_];
__device__ float g_k[M_ * D_];
__device__ float g_v[M_ * D_];
__device__ float g_ctx[M_ * D_];
__device__ float g_gate[M_];
__device__ float g_hsr[M_ * D_];    // tf32-rounded hidden_states
__device__ float g_wqr[D_ * D_];
__device__ float g_wkr[D_ * D_];
__device__ float g_wvr[D_ * D_];
__device__ float g_wor[D_ * D_];

// ============================================================
// helpers
// ============================================================
__device__ __forceinline__ float tf32r(float x) {
    uint32_t u;
    asm("cvt.rna.tf32.f32 %0, %1;" : "=r"(u) : "f"(x));
    return __uint_as_float(u);
}
__device__ __forceinline__ uint32_t tf32u(float x) {
    uint32_t u;
    asm("cvt.rna.tf32.f32 %0, %1;" : "=r"(u) : "f"(x));
    return u;
}
__device__ __forceinline__ void mma_tf32(float4& d, const uint32_t a[4], uint32_t b0, uint32_t b1) {
    asm volatile(
        "mma.sync.aligned.m16n8k8.row.col.f32.tf32.tf32.f32 "
        "{%0,%1,%2,%3}, {%4,%5,%6,%7}, {%8,%9}, {%0,%1,%2,%3};"
        : "+f"(d.x), "+f"(d.y), "+f"(d.z), "+f"(d.w)
        : "r"(a[0]), "r"(a[1]), "r"(a[2]), "r"(a[3]), "r"(b0), "r"(b1));
}
__device__ __forceinline__ void cp16(uint32_t saddr, const void* gptr) {
    asm volatile("cp.async.cg.shared.global [%0], [%1], 16;" :: "r"(saddr), "l"(gptr));
}
#define CP_COMMIT() asm volatile("cp.async.commit_group;")
#define CP_WAIT1()  asm volatile("cp.async.wait_group 1;")

// ============================================================
// elementwise tf32 pre-round (n must be multiple of 1024)
// ============================================================
__global__ __launch_bounds__(256) void round_copy(const float* __restrict__ in,
                                                  float* __restrict__ out)
{
    int i = (blockIdx.x * 256 + threadIdx.x) * 4;
    float4 v = *(const float4*)(in + i);
    v.x = tf32r(v.x); v.y = tf32r(v.y); v.z = tf32r(v.z); v.w = tf32r(v.w);
    *(float4*)(out + i) = v;
}

// ============================================================
// tf32 GEMM + bias, cp.async double-buffered.
// Inputs pre-rounded to tf32. 128x128 tile, BK=32, 256 threads.
// round_out=1 -> store tf32-rounded (feeds later MMAs).
// dyn smem: 2*(128*36 + 32*136) floats = 71680 B
// ============================================================
#define GA_ST (128 * 36)
#define GB_ST (32 * 136)

__global__ __launch_bounds__(256, 2) void gemm_v2(const float* __restrict__ A,
                                                  const float* __restrict__ W,
                                                  const float* __restrict__ bias,
                                                  float* __restrict__ C,
                                                  int round_out)
{
    extern __shared__ float sm[];
    float* Asm = sm;                 // 2 stages of [128][36]
    float* Bsm = sm + 2 * GA_ST;     // 2 stages of [32][136]
    uint32_t sA = (uint32_t)__cvta_generic_to_shared(Asm);
    uint32_t sB = (uint32_t)__cvta_generic_to_shared(Bsm);

    const int tid  = threadIdx.x;
    const int lane = tid & 31;
    const int warp = tid >> 5;
    const int wm = warp & 1;
    const int wn = warp >> 1;
    const int g  = lane >> 2;
    const int t4 = lane & 3;

    const int m0 = blockIdx.y * 128;
    const int n0 = blockIdx.x * 128;

    const int ar = tid >> 1;
    const int ak = (tid & 1) * 16;
    const int br = tid >> 3;
    const int bc = (tid & 7) * 16;

    float4 acc[4][4];
    #pragma unroll
    for (int mt = 0; mt < 4; mt++)
        #pragma unroll
        for (int nt = 0; nt < 4; nt++)
            acc[mt][nt] = make_float4(0.f, 0.f, 0.f, 0.f);

    // prologue: prefetch tile 0 into stage 0
    {
        #pragma unroll
        for (int i = 0; i < 4; i++)
            cp16(sA + (ar * 36 + ak + i * 4) * 4, &A[(size_t)(m0 + ar) * D_ + ak + i * 4]);
        #pragma unroll
        for (int i = 0; i < 4; i++)
            cp16(sB + (br * 136 + bc + i * 4) * 4, &W[(size_t)br * D_ + n0 + bc + i * 4]);
        CP_COMMIT();
    }

    for (int k0 = 0; k0 < D_; k0 += 32) {
        const int cur = (k0 >> 5) & 1;
        const int nxt = cur ^ 1;
        if (k0 + 32 < D_) {
            #pragma unroll
            for (int i = 0; i < 4; i++)
                cp16(sA + (nxt * GA_ST + ar * 36 + ak + i * 4) * 4,
                     &A[(size_t)(m0 + ar) * D_ + k0 + 32 + ak + i * 4]);
            #pragma unroll
            for (int i = 0; i < 4; i++)
                cp16(sB + (nxt * GB_ST + br * 136 + bc + i * 4) * 4,
                     &W[(size_t)(k0 + 32 + br) * D_ + n0 + bc + i * 4]);
        }
        CP_COMMIT();
        CP_WAIT1();
        __syncthreads();

        const float* Ac = Asm + cur * GA_ST;
        const float* Bc = Bsm + cur * GB_ST;
        #pragma unroll
        for (int ks = 0; ks < 4; ks++) {
            const int kb = ks * 8;
            uint32_t af[4][4];
            uint32_t bf[4][2];
            #pragma unroll
            for (int mt = 0; mt < 4; mt++) {
                int row = wm * 64 + mt * 16 + g;
                af[mt][0] = __float_as_uint(Ac[row * 36 + kb + t4]);
                af[mt][1] = __float_as_uint(Ac[(row + 8) * 36 + kb + t4]);
                af[mt][2] = __float_as_uint(Ac[row * 36 + kb + t4 + 4]);
                af[mt][3] = __float_as_uint(Ac[(row + 8) * 36 + kb + t4 + 4]);
            }
            #pragma unroll
            for (int nt = 0; nt < 4; nt++) {
                int col = wn * 32 + nt * 8 + g;
                bf[nt][0] = __float_as_uint(Bc[(kb + t4) * 136 + col]);
                bf[nt][1] = __float_as_uint(Bc[(kb + t4 + 4) * 136 + col]);
            }
            #pragma unroll
            for (int mt = 0; mt < 4; mt++)
                #pragma unroll
                for (int nt = 0; nt < 4; nt++)
                    mma_tf32(acc[mt][nt], af[mt], bf[nt][0], bf[nt][1]);
        }
        __syncthreads();
    }

    #pragma unroll
    for (int nt = 0; nt < 4; nt++) {
        int col = n0 + wn * 32 + nt * 8 + t4 * 2;
        float2 bb = *(const float2*)&bias[col];
        #pragma unroll
        for (int mt = 0; mt < 4; mt++) {
            int row = m0 + wm * 64 + mt * 16 + g;
            float2 o;
            o.x = acc[mt][nt].x + bb.x;
            o.y = acc[mt][nt].y + bb.y;
            if (round_out) { o.x = tf32r(o.x); o.y = tf32r(o.y); }
            *(float2*)&C[(size_t)row * D_ + col] = o;
            o.x = acc[mt][nt].z + bb.x;
            o.y = acc[mt][nt].w + bb.y;
            if (round_out) { o.x = tf32r(o.x); o.y = tf32r(o.y); }
            *(float2*)&C[(size_t)(row + 8) * D_ + col] = o;
        }
    }
}

// ============================================================
// Gating
// ============================================================
__global__ __launch_bounds__(256) void gate_kernel(const float* __restrict__ hs,
                                                   const float* __restrict__ gf,
                                                   const float* __restrict__ gb,
                                                   float* __restrict__ gate)
{
    __shared__ float red[256];
    int row = blockIdx.x;
    const float* p = hs + (size_t)row * D_;
    float sum = 0.f;
    for (int i = threadIdx.x; i < D_; i += 256) sum += p[i];
    red[threadIdx.x] = sum;
    __syncthreads();
    #pragma unroll
    for (int st = 128; st > 0; st >>= 1) {
        if (threadIdx.x < st) red[threadIdx.x] += red[threadIdx.x + st];
        __syncthreads();
    }
    if (threadIdx.x == 0) {
        float mean = red[0] * (1.0f / D_);
        float z = gf[0] * mean + gb[0];
        gate[row] = 1.0f / (1.0f + expf(-z));
    }
}

// ============================================================
// Tensor-core flash attention, cp.async double-buffered.
// q/k/v pre-rounded tf32. P aliases current K stage.
// dyn smem: 2*64*68 + 2*64*72 floats = 71680 B
// ============================================================
#define SC_ (0.125f * 1.44269504f)   // 1/sqrt(64) * log2(e)
#define AK_ST (64 * 68)
#define AV_ST (64 * 72)

__global__ __launch_bounds__(128) void attn_mma(const float* __restrict__ q,
                                                const float* __restrict__ k,
                                                const float* __restrict__ v,
                                                const float* __restrict__ gate,
                                                float* __restrict__ ctx)
{
    extern __shared__ float sm[];
    float* Kst = sm;                 // 2 stages of [64][68]
    float* Vst = sm + 2 * AK_ST;     // 2 stages of [64][72]
    uint32_t sK = (uint32_t)__cvta_generic_to_shared(Kst);
    uint32_t sV = (uint32_t)__cvta_generic_to_shared(Vst);

    const int b  = blockIdx.z;
    const int h  = blockIdx.y;
    const int q0 = blockIdx.x * 64;
    const int tid  = threadIdx.x;
    const int lane = tid & 31;
    const int w    = tid >> 5;
    const int g  = lane >> 2;
    const int t4 = lane & 3;
    const int wrow = w * 16;

    // ---- stage Q tile through Kst stage0 (plain), pull fragments ----
    #pragma unroll
    for (int i = 0; i < 8; i++) {
        int e = tid + i * 128;
        int row = e >> 4, f = e & 15;
        *(float4*)&Kst[row * 68 + f * 4] =
            *(const float4*)(q + ((size_t)(b * S_ + q0 + row)) * D_ + h * DH_ + f * 4);
    }
    __syncthreads();
    uint32_t aq[8][4];
    #pragma unroll
    for (int ks = 0; ks < 8; ks++) {
        int kb = ks * 8;
        aq[ks][0] = __float_as_uint(Kst[(wrow + g) * 68 + kb + t4]);
        aq[ks][1] = __float_as_uint(Kst[(wrow + 8 + g) * 68 + kb + t4]);
        aq[ks][2] = __float_as_uint(Kst[(wrow + g) * 68 + kb + t4 + 4]);
        aq[ks][3] = __float_as_uint(Kst[(wrow + 8 + g) * 68 + kb + t4 + 4]);
    }
    __syncthreads();

    float4 accO[8];
    #pragma unroll
    for (int nt = 0; nt < 8; nt++) accO[nt] = make_float4(0.f, 0.f, 0.f, 0.f);
    float mxlo = -1e30f, mxhi = -1e30f, llo = 0.f, lhi = 0.f;

    const int ldrow = tid >> 4;         // 0..7 base rows per pass
    const int ldf   = (tid & 15) * 4;   // float offset within 64

    // prologue: prefetch chunk 0 into stage 0
    #pragma unroll
    for (int i = 0; i < 8; i++) {
        int row = ldrow + i * 8;
        size_t off = ((size_t)(b * S_ + row)) * D_ + h * DH_ + ldf;
        cp16(sK + (row * 68 + ldf) * 4, k + off);
        cp16(sV + (row * 72 + ldf) * 4, v + off);
    }
    CP_COMMIT();

    for (int c = 0; c < S_ / 64; c++) {
        const int cur = c & 1;
        const int nxt = cur ^ 1;
        if (c + 1 < S_ / 64) {
            #pragma unroll
            for (int i = 0; i < 8; i++) {
                int row = ldrow + i * 8;
                size_t off = ((size_t)(b * S_ + (c + 1) * 64 + row)) * D_ + h * DH_ + ldf;
                cp16(sK + (nxt * AK_ST + row * 68 + ldf) * 4, k + off);
                cp16(sV + (nxt * AV_ST + row * 72 + ldf) * 4, v + off);
            }
        }
        CP_COMMIT();
        CP_WAIT1();
        __syncthreads();

        float* Kc = Kst + cur * AK_ST;
        float* Vc = Vst + cur * AV_ST;

        // ---- scores = Q @ K^T ----
        float4 s[8];
        #pragma unroll
        for (int nt = 0; nt < 8; nt++) {
            float4 acc = make_float4(0.f, 0.f, 0.f, 0.f);
            #pragma unroll
            for (int ks = 0; ks < 8; ks++) {
                int kb = ks * 8;
                uint32_t b0 = __float_as_uint(Kc[(nt * 8 + g) * 68 + kb + t4]);
                uint32_t b1 = __float_as_uint(Kc[(nt * 8 + g) * 68 + kb + t4 + 4]);
                mma_tf32(acc, aq[ks], b0, b1);
            }
            s[nt] = acc;
        }
        __syncthreads();   // K reads done before P aliases Kc

        // ---- online softmax ----
        float mlo = -1e30f, mhi = -1e30f;
        #pragma unroll
        for (int nt = 0; nt < 8; nt++) {
            mlo = fmaxf(mlo, fmaxf(s[nt].x, s[nt].y));
            mhi = fmaxf(mhi, fmaxf(s[nt].z, s[nt].w));
        }
        mlo = fmaxf(mlo, __shfl_xor_sync(0xffffffffu, mlo, 1));
        mlo = fmaxf(mlo, __shfl_xor_sync(0xffffffffu, mlo, 2));
        mhi = fmaxf(mhi, __shfl_xor_sync(0xffffffffu, mhi, 1));
        mhi = fmaxf(mhi, __shfl_xor_sync(0xffffffffu, mhi, 2));

        float mnlo = fmaxf(mxlo, mlo);
        float mnhi = fmaxf(mxhi, mhi);
        float clo = exp2f((mxlo - mnlo) * SC_);
        float chi = exp2f((mxhi - mnhi) * SC_);

        float slo = 0.f, shi = 0.f;
        #pragma unroll
        for (int nt = 0; nt < 8; nt++) {
            s[nt].x = exp2f((s[nt].x - mnlo) * SC_);
            s[nt].y = exp2f((s[nt].y - mnlo) * SC_);
            s[nt].z = exp2f((s[nt].z - mnhi) * SC_);
            s[nt].w = exp2f((s[nt].w - mnhi) * SC_);
            slo += s[nt].x + s[nt].y;
            shi += s[nt].z + s[nt].w;
        }
        slo += __shfl_xor_sync(0xffffffffu, slo, 1);
        slo += __shfl_xor_sync(0xffffffffu, slo, 2);
        shi += __shfl_xor_sync(0xffffffffu, shi, 1);
        shi += __shfl_xor_sync(0xffffffffu, shi, 2);
        llo = llo * clo + slo;
        lhi = lhi * chi + shi;
        mxlo = mnlo; mxhi = mnhi;

        #pragma unroll
        for (int nt = 0; nt < 8; nt++) {
            accO[nt].x *= clo; accO[nt].y *= clo;
            accO[nt].z *= chi; accO[nt].w *= chi;
        }

        // ---- store P (tf32) to warp-private rows of Kc ----
        #pragma unroll
        for (int nt = 0; nt < 8; nt++) {
            int col = nt * 8 + 2 * t4;
            Kc[(wrow + g) * 68 + col]         = __uint_as_float(tf32u(s[nt].x));
            Kc[(wrow + g) * 68 + col + 1]     = __uint_as_float(tf32u(s[nt].y));
            Kc[(wrow + 8 + g) * 68 + col]     = __uint_as_float(tf32u(s[nt].z));
            Kc[(wrow + 8 + g) * 68 + col + 1] = __uint_as_float(tf32u(s[nt].w));
        }
        __syncwarp();

        // ---- O += P @ V ----
        #pragma unroll
        for (int ks = 0; ks < 8; ks++) {
            int kb = ks * 8;
            uint32_t ap[4];
            ap[0] = __float_as_uint(Kc[(wrow + g) * 68 + kb + t4]);
            ap[1] = __float_as_uint(Kc[(wrow + 8 + g) * 68 + kb + t4]);
            ap[2] = __float_as_uint(Kc[(wrow + g) * 68 + kb + t4 + 4]);
            ap[3] = __float_as_uint(Kc[(wrow + 8 + g) * 68 + kb + t4 + 4]);
            #pragma unroll
            for (int nt = 0; nt < 8; nt++) {
                uint32_t b0 = __float_as_uint(Vc[(kb + t4) * 72 + nt * 8 + g]);
                uint32_t b1 = __float_as_uint(Vc[(kb + t4 + 4) * 72 + nt * 8 + g]);
                mma_tf32(accO[nt], ap, b0, b1);
            }
        }
        __syncthreads();   // stage reads done before it becomes a prefetch target
    }

    // ---- epilogue: gate/l scale, tf32-round (feeds Wo GEMM), store ----
    int qlo = q0 + wrow + g;
    int qhi = qlo + 8;
    float glo = gate[b * S_ + qlo] / llo;
    float ghi = gate[b * S_ + qhi] / lhi;
    #pragma unroll
    for (int nt = 0; nt < 8; nt++) {
        int col = h * DH_ + nt * 8 + 2 * t4;
        float2 o1;
        o1.x = tf32r(accO[nt].x * glo);
        o1.y = tf32r(accO[nt].y * glo);
        *(float2*)&ctx[((size_t)(b * S_ + qlo)) * D_ + col] = o1;
        float2 o2;
        o2.x = tf32r(accO[nt].z * ghi);
        o2.y = tf32r(accO[nt].w * ghi);
        *(float2*)&ctx[((size_t)(b * S_ + qhi)) * D_ + col] = o2;
    }
}

// ============================================================
// Launch
// ============================================================
extern "C" void kernel_launch(void* const* d_in, const int* in_sizes, int n_in,
                              void* d_out, int out_size)
{
    const float* hs = (const float*)d_in[0];
    const float* Wq = (const float*)d_in[1];
    const float* bq = (const float*)d_in[2];
    const float* Wk = (const float*)d_in[3];
    const float* bk = (const float*)d_in[4];
    const float* Wv = (const float*)d_in[5];
    const float* bv = (const float*)d_in[6];
    const float* Wo = (const float*)d_in[7];
    const float* bo = (const float*)d_in[8];
    const float* gf = (const float*)d_in[9];
    const float* gb = (const float*)d_in[10];
    float* out = (float*)d_out;

    float *qp, *kp, *vp, *cp, *gp, *hsr, *wq, *wk, *wv, *wo;
    cudaGetSymbolAddress((void**)&qp, g_q);
    cudaGetSymbolAddress((void**)&kp, g_k);
    cudaGetSymbolAddress((void**)&vp, g_v);
    cudaGetSymbolAddress((void**)&cp, g_ctx);
    cudaGetSymbolAddress((void**)&gp, g_gate);
    cudaGetSymbolAddress((void**)&hsr, g_hsr);
    cudaGetSymbolAddress((void**)&wq, g_wqr);
    cudaGetSymbolAddress((void**)&wk, g_wkr);
    cudaGetSymbolAddress((void**)&wv, g_wvr);
    cudaGetSymbolAddress((void**)&wo, g_wor);

    const int SMEM_G = 71680;
    cudaFuncSetAttribute(gemm_v2, cudaFuncAttributeMaxDynamicSharedMemorySize, SMEM_G);
    cudaFuncSetAttribute(attn_mma, cudaFuncAttributeMaxDynamicSharedMemorySize, SMEM_G);

    // pre-round inputs to tf32 (once per call)
    round_copy<<<(M_ * D_) / 1024, 256>>>(hs, hsr);
    round_copy<<<(D_ * D_) / 1024, 256>>>(Wq, wq);
    round_copy<<<(D_ * D_) / 1024, 256>>>(Wk, wk);
    round_copy<<<(D_ * D_) / 1024, 256>>>(Wv, wv);
    round_copy<<<(D_ * D_) / 1024, 256>>>(Wo, wo);

    dim3 gg(D_ / 128, M_ / 128);   // 8 x 32 = 256 blocks

    gemm_v2<<<gg, 256, SMEM_G>>>(hsr, wq, bq, qp, 1);
    gemm_v2<<<gg, 256, SMEM_G>>>(hsr, wk, bk, kp, 1);
    gemm_v2<<<gg, 256, SMEM_G>>>(hsr, wv, bv, vp, 1);
    gate_kernel<<<M_, 256>>>(hs, gf, gb, gp);
    attn_mma<<<dim3(S_ / 64, H_, B_), 128, SMEM_G>>>(qp, kp, vp, gp, cp);
    gemm_v2<<<gg, 256, SMEM_G>>>(cp, wo, bo, out, 0);
}

// round 6
// speedup vs baseline: 7.2069x; 1.9860x over previous
#include <cuda_runtime.h>
#include <cuda_fp16.h>
#include <math.h>
#include <stdint.h>

#define B_ 2
#define S_ 2048
#define D_ 1024
#define H_ 16
#define DH_ 64
#define M_ (B_ * S_)   // 4096 token rows

// -------- scratch (allocation-free: __device__ globals) --------
__device__ __half g_hsh[M_ * D_];   // fp16 hidden_states
__device__ __half g_qh[M_ * D_];
__device__ __half g_kh[M_ * D_];
__device__ __half g_vt[M_ * D_];    // V transposed: [b][d_model][s]
__device__ __half g_ch[M_ * D_];    // ctx fp16
__device__ float  g_gate[M_];
__device__ __half g_wqt[D_ * D_];   // fp16, transposed weights [n][k]
__device__ __half g_wkt[D_ * D_];
__device__ __half g_wvt[D_ * D_];
__device__ __half g_wot[D_ * D_];

// ============================================================
// helpers
// ============================================================
__device__ __forceinline__ void mma_f16(float4& d, const uint32_t a[4], uint32_t b0, uint32_t b1) {
    asm volatile(
        "mma.sync.aligned.m16n8k16.row.col.f32.f16.f16.f32 "
        "{%0,%1,%2,%3}, {%4,%5,%6,%7}, {%8,%9}, {%0,%1,%2,%3};"
        : "+f"(d.x), "+f"(d.y), "+f"(d.z), "+f"(d.w)
        : "r"(a[0]), "r"(a[1]), "r"(a[2]), "r"(a[3]), "r"(b0), "r"(b1));
}
__device__ __forceinline__ void cp16(uint32_t saddr, const void* gptr) {
    asm volatile("cp.async.cg.shared.global [%0], [%1], 16;" :: "r"(saddr), "l"(gptr));
}
#define CP_COMMIT() asm volatile("cp.async.commit_group;")
#define CP_WAIT1()  asm volatile("cp.async.wait_group 1;")

// ============================================================
// hs -> fp16 + gating (one pass)
// ============================================================
__global__ __launch_bounds__(256) void hs_pre(const float* __restrict__ hs,
                                              __half* __restrict__ hsh,
                                              const float* __restrict__ gf,
                                              const float* __restrict__ gb,
                                              float* __restrict__ gate)
{
    __shared__ float red[8];
    int row = blockIdx.x;
    int t = threadIdx.x;
    float4 v = *(const float4*)(hs + (size_t)row * D_ + t * 4);
    float s = (v.x + v.y) + (v.z + v.w);
    __half2* dst = (__half2*)(hsh + (size_t)row * D_ + t * 4);
    dst[0] = __floats2half2_rn(v.x, v.y);
    dst[1] = __floats2half2_rn(v.z, v.w);
    #pragma unroll
    for (int st = 16; st > 0; st >>= 1) s += __shfl_xor_sync(0xffffffffu, s, st);
    if ((t & 31) == 0) red[t >> 5] = s;
    __syncthreads();
    if (t == 0) {
        float tot = 0.f;
        #pragma unroll
        for (int i = 0; i < 8; i++) tot += red[i];
        float z = gf[0] * (tot * (1.0f / D_)) + gb[0];
        gate[row] = 1.0f / (1.0f + expf(-z));
    }
}

// ============================================================
// weight transpose + fp16: dst[n][k] = h(src[k][n]); z selects weight
// ============================================================
__global__ __launch_bounds__(256) void wt_pre(const float* __restrict__ w0,
                                              const float* __restrict__ w1,
                                              const float* __restrict__ w2,
                                              const float* __restrict__ w3,
                                              __half* __restrict__ o0,
                                              __half* __restrict__ o1,
                                              __half* __restrict__ o2,
                                              __half* __restrict__ o3)
{
    __shared__ float t[32][33];
    const float* src = (blockIdx.z == 0) ? w0 : (blockIdx.z == 1) ? w1 : (blockIdx.z == 2) ? w2 : w3;
    __half*      dst = (blockIdx.z == 0) ? o0 : (blockIdx.z == 1) ? o1 : (blockIdx.z == 2) ? o2 : o3;
    int k0 = blockIdx.y * 32, n0 = blockIdx.x * 32;
    int tx = threadIdx.x & 31, ty = threadIdx.x >> 5;
    #pragma unroll
    for (int r = 0; r < 4; r++)
        t[ty + 8 * r][tx] = src[(size_t)(k0 + ty + 8 * r) * D_ + n0 + tx];
    __syncthreads();
    #pragma unroll
    for (int r = 0; r < 4; r++)
        dst[(size_t)(n0 + ty + 8 * r) * D_ + k0 + tx] = __float2half_rn(t[tx][ty + 8 * r]);
}

// ============================================================
// fp16 GEMM + bias: C[M,1024] = A @ Wt^T + bias
// A [M,K] fp16, Wt [N,K] fp16. 128x128 tile, BK=32, 256 thr (8 warps 2x4),
// cp.async double-buffered. mode: 0=float out, 1=half out, 2=half Vt out.
// dyn smem: 4 * 128*40 halves = 40960 B
// ============================================================
#define GH_LD 40
#define GH_ST (128 * GH_LD)     // halves per operand-stage

__global__ __launch_bounds__(256) void gemm_h(const __half* __restrict__ A,
                                              const __half* __restrict__ Wt,
                                              const float* __restrict__ bias,
                                              void* __restrict__ Cout,
                                              int mode)
{
    extern __shared__ __half smh[];
    __half* Ast = smh;                   // 2 stages
    __half* Bst = smh + 2 * GH_ST;       // 2 stages
    uint32_t sA = (uint32_t)__cvta_generic_to_shared(Ast);
    uint32_t sB = (uint32_t)__cvta_generic_to_shared(Bst);

    const int tid  = threadIdx.x;
    const int lane = tid & 31;
    const int warp = tid >> 5;
    const int wm = warp & 1;
    const int wn = warp >> 1;
    const int g  = lane >> 2;
    const int t4 = lane & 3;

    const int m0 = blockIdx.y * 128;
    const int n0 = blockIdx.x * 128;

    // cp geometry: tile = 128 rows x 32 halves (4 x 16B chunks per row)
    const int lrow = tid >> 2;          // 0..63, two passes -> 128 rows
    const int lch  = (tid & 3) * 8;     // half offset

    float4 acc[4][4];
    #pragma unroll
    for (int mt = 0; mt < 4; mt++)
        #pragma unroll
        for (int nt = 0; nt < 4; nt++)
            acc[mt][nt] = make_float4(0.f, 0.f, 0.f, 0.f);

    // prologue: tile 0 -> stage 0
    #pragma unroll
    for (int i = 0; i < 2; i++) {
        int row = lrow + i * 64;
        cp16(sA + (row * GH_LD + lch) * 2, &A[(size_t)(m0 + row) * D_ + lch]);
        cp16(sB + (row * GH_LD + lch) * 2, &Wt[(size_t)(n0 + row) * D_ + lch]);
    }
    CP_COMMIT();

    for (int k0 = 0; k0 < D_; k0 += 32) {
        const int cur = (k0 >> 5) & 1;
        const int nxt = cur ^ 1;
        if (k0 + 32 < D_) {
            #pragma unroll
            for (int i = 0; i < 2; i++) {
                int row = lrow + i * 64;
                cp16(sA + (nxt * GH_ST + row * GH_LD + lch) * 2,
                     &A[(size_t)(m0 + row) * D_ + k0 + 32 + lch]);
                cp16(sB + (nxt * GH_ST + row * GH_LD + lch) * 2,
                     &Wt[(size_t)(n0 + row) * D_ + k0 + 32 + lch]);
            }
        }
        CP_COMMIT();
        CP_WAIT1();
        __syncthreads();

        const __half* Ac = Ast + cur * GH_ST;
        const __half* Bc = Bst + cur * GH_ST;
        #pragma unroll
        for (int ks = 0; ks < 2; ks++) {
            const int kf = ks * 16 + 2 * t4;
            uint32_t af[4][4];
            uint32_t bf[4][2];
            #pragma unroll
            for (int mt = 0; mt < 4; mt++) {
                int row = wm * 64 + mt * 16 + g;
                af[mt][0] = *(const uint32_t*)&Ac[row * GH_LD + kf];
                af[mt][1] = *(const uint32_t*)&Ac[(row + 8) * GH_LD + kf];
                af[mt][2] = *(const uint32_t*)&Ac[row * GH_LD + kf + 8];
                af[mt][3] = *(const uint32_t*)&Ac[(row + 8) * GH_LD + kf + 8];
            }
            #pragma unroll
            for (int nt = 0; nt < 4; nt++) {
                int n = wn * 32 + nt * 8 + g;
                bf[nt][0] = *(const uint32_t*)&Bc[n * GH_LD + kf];
                bf[nt][1] = *(const uint32_t*)&Bc[n * GH_LD + kf + 8];
            }
            #pragma unroll
            for (int mt = 0; mt < 4; mt++)
                #pragma unroll
                for (int nt = 0; nt < 4; nt++)
                    mma_f16(acc[mt][nt], af[mt], bf[nt][0], bf[nt][1]);
        }
        __syncthreads();
    }

    if (mode == 0) {
        float* C = (float*)Cout;
        #pragma unroll
        for (int nt = 0; nt < 4; nt++) {
            int col = n0 + wn * 32 + nt * 8 + t4 * 2;
            float2 bb = *(const float2*)&bias[col];
            #pragma unroll
            for (int mt = 0; mt < 4; mt++) {
                int row = m0 + wm * 64 + mt * 16 + g;
                float2 o;
                o.x = acc[mt][nt].x + bb.x; o.y = acc[mt][nt].y + bb.y;
                *(float2*)&C[(size_t)row * D_ + col] = o;
                o.x = acc[mt][nt].z + bb.x; o.y = acc[mt][nt].w + bb.y;
                *(float2*)&C[(size_t)(row + 8) * D_ + col] = o;
            }
        }
    } else if (mode == 1) {
        __half* C = (__half*)Cout;
        #pragma unroll
        for (int nt = 0; nt < 4; nt++) {
            int col = n0 + wn * 32 + nt * 8 + t4 * 2;
            float2 bb = *(const float2*)&bias[col];
            #pragma unroll
            for (int mt = 0; mt < 4; mt++) {
                int row = m0 + wm * 64 + mt * 16 + g;
                *(__half2*)&C[(size_t)row * D_ + col] =
                    __floats2half2_rn(acc[mt][nt].x + bb.x, acc[mt][nt].y + bb.y);
                *(__half2*)&C[(size_t)(row + 8) * D_ + col] =
                    __floats2half2_rn(acc[mt][nt].z + bb.x, acc[mt][nt].w + bb.y);
            }
        }
    } else {
        // mode 2: transpose via smem, write Vt[b][n0+col][s]
        __syncthreads();
        __half* T = smh;   // [128 cols][144 rows pad]
        #pragma unroll
        for (int nt = 0; nt < 4; nt++) {
            int col = wn * 32 + nt * 8 + 2 * t4;
            float2 bb = *(const float2*)&bias[n0 + col];
            #pragma unroll
            for (int mt = 0; mt < 4; mt++) {
                int row = wm * 64 + mt * 16 + g;
                T[col * 144 + row]           = __float2half_rn(acc[mt][nt].x + bb.x);
                T[(col + 1) * 144 + row]     = __float2half_rn(acc[mt][nt].y + bb.y);
                T[col * 144 + row + 8]       = __float2half_rn(acc[mt][nt].z + bb.x);
                T[(col + 1) * 144 + row + 8] = __float2half_rn(acc[mt][nt].w + bb.y);
            }
        }
        __syncthreads();
        __half* Vt = (__half*)Cout;
        int colc  = tid >> 1;
        int roff  = (tid & 1) * 64;
        int bb2   = m0 >> 11;             // batch
        int ms    = (m0 & (S_ - 1)) + roff;
        const uint4* src = (const uint4*)&T[colc * 144 + roff];
        uint4* dst = (uint4*)(Vt + ((size_t)bb2 * D_ + n0 + colc) * S_ + ms);
        #pragma unroll
        for (int i = 0; i < 8; i++) dst[i] = src[i];
    }
}

// ============================================================
// fp16 tensor-core flash attention + post-softmax gate.
// Block = 128 thr (4 warps) = 64-query tile of one (b,h).
// K stage [64][72] halves; V stage = Vt slice [64 d][72 keys].
// P (half) aliases current K stage. cp.async double-buffered.
// dyn smem: 4 * 64*72 halves = 36864 B
// ============================================================
#define SC_ (0.125f * 1.44269504f)   // 1/sqrt(64) * log2(e)
#define AH_ST (64 * 72)              // halves per stage

__global__ __launch_bounds__(128) void attn_h(const __half* __restrict__ q,
                                              const __half* __restrict__ k,
                                              const __half* __restrict__ vt,
                                              const float* __restrict__ gate,
                                              __half* __restrict__ ctx)
{
    extern __shared__ __half smh[];
    __half* Kst = smh;                 // 2 stages [64][72]
    __half* Vst = smh + 2 * AH_ST;     // 2 stages [64 d][72 keys]
    uint32_t sK = (uint32_t)__cvta_generic_to_shared(Kst);
    uint32_t sV = (uint32_t)__cvta_generic_to_shared(Vst);

    const int b  = blockIdx.z;
    const int h  = blockIdx.y;
    const int q0 = blockIdx.x * 64;
    const int tid  = threadIdx.x;
    const int lane = tid & 31;
    const int w    = tid >> 5;
    const int g  = lane >> 2;
    const int t4 = lane & 3;
    const int wrow = w * 16;

    // ---- stage Q tile (plain) through Kst stage0, pull fragments ----
    #pragma unroll
    for (int i = 0; i < 4; i++) {
        int e = tid + i * 128;          // 512 chunks of 8 halves
        int row = e >> 3, ch = (e & 7) * 8;
        *(uint4*)&Kst[row * 72 + ch] =
            *(const uint4*)(q + ((size_t)(b * S_ + q0 + row)) * D_ + h * DH_ + ch);
    }
    __syncthreads();
    uint32_t aq[4][4];
    #pragma unroll
    for (int ks = 0; ks < 4; ks++) {
        int kf = ks * 16 + 2 * t4;
        aq[ks][0] = *(const uint32_t*)&Kst[(wrow + g) * 72 + kf];
        aq[ks][1] = *(const uint32_t*)&Kst[(wrow + 8 + g) * 72 + kf];
        aq[ks][2] = *(const uint32_t*)&Kst[(wrow + g) * 72 + kf + 8];
        aq[ks][3] = *(const uint32_t*)&Kst[(wrow + 8 + g) * 72 + kf + 8];
    }
    __syncthreads();

    float4 accO[8];
    #pragma unroll
    for (int nt = 0; nt < 8; nt++) accO[nt] = make_float4(0.f, 0.f, 0.f, 0.f);
    float mxlo = -1e30f, mxhi = -1e30f, llo = 0.f, lhi = 0.f;

    const int lrow = tid >> 3;          // 0..15, 4 passes -> 64 rows
    const int lch  = (tid & 7) * 8;     // half offset in 64

    const __half* kbase  = k  + ((size_t)b * S_) * D_ + h * DH_;
    const __half* vtbase = vt + ((size_t)b * D_ + h * DH_) * S_;

    // prologue: chunk 0 -> stage 0
    #pragma unroll
    for (int i = 0; i < 4; i++) {
        int row = lrow + i * 16;
        cp16(sK + (row * 72 + lch) * 2, kbase + (size_t)row * D_ + lch);
        cp16(sV + (row * 72 + lch) * 2, vtbase + (size_t)row * S_ + lch);
    }
    CP_COMMIT();

    for (int c = 0; c < S_ / 64; c++) {
        const int cur = c & 1;
        const int nxt = cur ^ 1;
        if (c + 1 < S_ / 64) {
            const int kc = (c + 1) * 64;
            #pragma unroll
            for (int i = 0; i < 4; i++) {
                int row = lrow + i * 16;
                cp16(sK + (nxt * AH_ST + row * 72 + lch) * 2,
                     kbase + (size_t)(kc + row) * D_ + lch);
                cp16(sV + (nxt * AH_ST + row * 72 + lch) * 2,
                     vtbase + (size_t)row * S_ + kc + lch);
            }
        }
        CP_COMMIT();
        CP_WAIT1();
        __syncthreads();

        __half* Kc = Kst + cur * AH_ST;
        __half* Vc = Vst + cur * AH_ST;

        // ---- scores = Q @ K^T ----
        float4 s[8];
        #pragma unroll
        for (int nt = 0; nt < 8; nt++) {
            float4 acc = make_float4(0.f, 0.f, 0.f, 0.f);
            #pragma unroll
            for (int ks = 0; ks < 4; ks++) {
                int kf = ks * 16 + 2 * t4;
                uint32_t b0 = *(const uint32_t*)&Kc[(nt * 8 + g) * 72 + kf];
                uint32_t b1 = *(const uint32_t*)&Kc[(nt * 8 + g) * 72 + kf + 8];
                mma_f16(acc, aq[ks], b0, b1);
            }
            s[nt] = acc;
        }
        __syncthreads();   // K reads done before P aliases Kc

        // ---- online softmax ----
        float mlo = -1e30f, mhi = -1e30f;
        #pragma unroll
        for (int nt = 0; nt < 8; nt++) {
            mlo = fmaxf(mlo, fmaxf(s[nt].x, s[nt].y));
            mhi = fmaxf(mhi, fmaxf(s[nt].z, s[nt].w));
        }
        mlo = fmaxf(mlo, __shfl_xor_sync(0xffffffffu, mlo, 1));
        mlo = fmaxf(mlo, __shfl_xor_sync(0xffffffffu, mlo, 2));
        mhi = fmaxf(mhi, __shfl_xor_sync(0xffffffffu, mhi, 1));
        mhi = fmaxf(mhi, __shfl_xor_sync(0xffffffffu, mhi, 2));

        float mnlo = fmaxf(mxlo, mlo);
        float mnhi = fmaxf(mxhi, mhi);
        float clo = exp2f((mxlo - mnlo) * SC_);
        float chi = exp2f((mxhi - mnhi) * SC_);

        float slo = 0.f, shi = 0.f;
        #pragma unroll
        for (int nt = 0; nt < 8; nt++) {
            s[nt].x = exp2f((s[nt].x - mnlo) * SC_);
            s[nt].y = exp2f((s[nt].y - mnlo) * SC_);
            s[nt].z = exp2f((s[nt].z - mnhi) * SC_);
            s[nt].w = exp2f((s[nt].w - mnhi) * SC_);
            slo += s[nt].x + s[nt].y;
            shi += s[nt].z + s[nt].w;
        }
        slo += __shfl_xor_sync(0xffffffffu, slo, 1);
        slo += __shfl_xor_sync(0xffffffffu, slo, 2);
        shi += __shfl_xor_sync(0xffffffffu, shi, 1);
        shi += __shfl_xor_sync(0xffffffffu, shi, 2);
        llo = llo * clo + slo;
        lhi = lhi * chi + shi;
        mxlo = mnlo; mxhi = mnhi;

        #pragma unroll
        for (int nt = 0; nt < 8; nt++) {
            accO[nt].x *= clo; accO[nt].y *= clo;
            accO[nt].z *= chi; accO[nt].w *= chi;
        }

        // ---- store P (half2) to warp-private rows of Kc ----
        #pragma unroll
        for (int nt = 0; nt < 8; nt++) {
            int col = nt * 8 + 2 * t4;
            *(__half2*)&Kc[(wrow + g) * 72 + col]     = __floats2half2_rn(s[nt].x, s[nt].y);
            *(__half2*)&Kc[(wrow + 8 + g) * 72 + col] = __floats2half2_rn(s[nt].z, s[nt].w);
        }
        __syncwarp();

        // ---- O += P @ V  (B from Vt [d][key], contiguous key-pairs) ----
        #pragma unroll
        for (int ks = 0; ks < 4; ks++) {
            int kf = ks * 16 + 2 * t4;
            uint32_t ap[4];
            ap[0] = *(const uint32_t*)&Kc[(wrow + g) * 72 + kf];
            ap[1] = *(const uint32_t*)&Kc[(wrow + 8 + g) * 72 + kf];
            ap[2] = *(const uint32_t*)&Kc[(wrow + g) * 72 + kf + 8];
            ap[3] = *(const uint32_t*)&Kc[(wrow + 8 + g) * 72 + kf + 8];
            #pragma unroll
            for (int nt = 0; nt < 8; nt++) {
                uint32_t b0 = *(const uint32_t*)&Vc[(nt * 8 + g) * 72 + kf];
                uint32_t b1 = *(const uint32_t*)&Vc[(nt * 8 + g) * 72 + kf + 8];
                mma_f16(accO[nt], ap, b0, b1);
            }
        }
        __syncthreads();   // stage reads done before it becomes a prefetch target
    }

    // ---- epilogue: gate/l scale, fp16 store (feeds Wo GEMM) ----
    int qlo = q0 + wrow + g;
    int qhi = qlo + 8;
    float glo = gate[b * S_ + qlo] / llo;
    float ghi = gate[b * S_ + qhi] / lhi;
    #pragma unroll
    for (int nt = 0; nt < 8; nt++) {
        int col = h * DH_ + nt * 8 + 2 * t4;
        *(__half2*)&ctx[((size_t)(b * S_ + qlo)) * D_ + col] =
            __floats2half2_rn(accO[nt].x * glo, accO[nt].y * glo);
        *(__half2*)&ctx[((size_t)(b * S_ + qhi)) * D_ + col] =
            __floats2half2_rn(accO[nt].z * ghi, accO[nt].w * ghi);
    }
}

// ============================================================
// Launch
// ============================================================
extern "C" void kernel_launch(void* const* d_in, const int* in_sizes, int n_in,
                              void* d_out, int out_size)
{
    const float* hs = (const float*)d_in[0];
    const float* Wq = (const float*)d_in[1];
    const float* bq = (const float*)d_in[2];
    const float* Wk = (const float*)d_in[3];
    const float* bk = (const float*)d_in[4];
    const float* Wv = (const float*)d_in[5];
    const float* bv = (const float*)d_in[6];
    const float* Wo = (const float*)d_in[7];
    const float* bo = (const float*)d_in[8];
    const float* gf = (const float*)d_in[9];
    const float* gb = (const float*)d_in[10];
    float* out = (float*)d_out;

    __half *hsh, *qh, *kh, *vtp, *ch, *wq, *wk, *wv, *wo;
    float *gp;
    cudaGetSymbolAddress((void**)&hsh, g_hsh);
    cudaGetSymbolAddress((void**)&qh, g_qh);
    cudaGetSymbolAddress((void**)&kh, g_kh);
    cudaGetSymbolAddress((void**)&vtp, g_vt);
    cudaGetSymbolAddress((void**)&ch, g_ch);
    cudaGetSymbolAddress((void**)&gp, g_gate);
    cudaGetSymbolAddress((void**)&wq, g_wqt);
    cudaGetSymbolAddress((void**)&wk, g_wkt);
    cudaGetSymbolAddress((void**)&wv, g_wvt);
    cudaGetSymbolAddress((void**)&wo, g_wot);

    const int SMEM_G = 40960;
    const int SMEM_A = 36864;
    cudaFuncSetAttribute(gemm_h, cudaFuncAttributeMaxDynamicSharedMemorySize, SMEM_G);
    cudaFuncSetAttribute(attn_h, cudaFuncAttributeMaxDynamicSharedMemorySize, SMEM_A);

    hs_pre<<<M_, 256>>>(hs, hsh, gf, gb, gp);
    wt_pre<<<dim3(32, 32, 4), 256>>>(Wq, Wk, Wv, Wo, wq, wk, wv, wo);

    dim3 gg(D_ / 128, M_ / 128);   // 8 x 32 = 256 blocks

    gemm_h<<<gg, 256, SMEM_G>>>(hsh, wq, bq, qh, 1);
    gemm_h<<<gg, 256, SMEM_G>>>(hsh, wk, bk, kh, 1);
    gemm_h<<<gg, 256, SMEM_G>>>(hsh, wv, bv, vtp, 2);
    attn_h<<<dim3(S_ / 64, H_, B_), 128, SMEM_A>>>(qh, kh, vtp, gp, ch);
    gemm_h<<<gg, 256, SMEM_G>>>(ch, wo, bo, out, 0);
}

// round 7
// speedup vs baseline: 7.9994x; 1.1100x over previous
#include <cuda_runtime.h>
#include <cuda_fp16.h>
#include <math.h>
#include <stdint.h>

#define B_ 2
#define S_ 2048
#define D_ 1024
#define H_ 16
#define DH_ 64
#define M_ (B_ * S_)   // 4096 token rows

// -------- scratch (allocation-free: __device__ globals) --------
__device__ __half g_hsh[M_ * D_];   // fp16 hidden_states
__device__ __half g_qh[M_ * D_];
__device__ __half g_kh[M_ * D_];
__device__ __half g_vt[M_ * D_];    // V transposed: [b][d_model][s]
__device__ __half g_ch[M_ * D_];    // ctx fp16
__device__ float  g_gate[M_];
__device__ __half g_wqt[D_ * D_];   // fp16, transposed weights [n][k]
__device__ __half g_wkt[D_ * D_];
__device__ __half g_wvt[D_ * D_];
__device__ __half g_wot[D_ * D_];

// ============================================================
// helpers
// ============================================================
__device__ __forceinline__ void mma_f16(float4& d, const uint32_t a[4], uint32_t b0, uint32_t b1) {
    asm volatile(
        "mma.sync.aligned.m16n8k16.row.col.f32.f16.f16.f32 "
        "{%0,%1,%2,%3}, {%4,%5,%6,%7}, {%8,%9}, {%0,%1,%2,%3};"
        : "+f"(d.x), "+f"(d.y), "+f"(d.z), "+f"(d.w)
        : "r"(a[0]), "r"(a[1]), "r"(a[2]), "r"(a[3]), "r"(b0), "r"(b1));
}
__device__ __forceinline__ void ldm4(uint32_t& r0, uint32_t& r1, uint32_t& r2, uint32_t& r3,
                                     uint32_t addr) {
    asm volatile("ldmatrix.sync.aligned.m8n8.x4.shared.b16 {%0,%1,%2,%3}, [%4];"
                 : "=r"(r0), "=r"(r1), "=r"(r2), "=r"(r3) : "r"(addr));
}
__device__ __forceinline__ void cp16(uint32_t saddr, const void* gptr) {
    asm volatile("cp.async.cg.shared.global [%0], [%1], 16;" :: "r"(saddr), "l"(gptr));
}
#define CP_COMMIT() asm volatile("cp.async.commit_group;")
#define CP_WAIT1()  asm volatile("cp.async.wait_group 1;")

__device__ __forceinline__ uint32_t f2h2(float a, float b) {
    __half2 h = __floats2half2_rn(a, b);
    return *(uint32_t*)&h;
}

// ============================================================
// hs -> fp16 + gating (one pass)
// ============================================================
__global__ __launch_bounds__(256) void hs_pre(const float* __restrict__ hs,
                                              __half* __restrict__ hsh,
                                              const float* __restrict__ gf,
                                              const float* __restrict__ gb,
                                              float* __restrict__ gate)
{
    __shared__ float red[8];
    int row = blockIdx.x;
    int t = threadIdx.x;
    float4 v = *(const float4*)(hs + (size_t)row * D_ + t * 4);
    float s = (v.x + v.y) + (v.z + v.w);
    __half2* dst = (__half2*)(hsh + (size_t)row * D_ + t * 4);
    dst[0] = __floats2half2_rn(v.x, v.y);
    dst[1] = __floats2half2_rn(v.z, v.w);
    #pragma unroll
    for (int st = 16; st > 0; st >>= 1) s += __shfl_xor_sync(0xffffffffu, s, st);
    if ((t & 31) == 0) red[t >> 5] = s;
    __syncthreads();
    if (t == 0) {
        float tot = 0.f;
        #pragma unroll
        for (int i = 0; i < 8; i++) tot += red[i];
        float z = gf[0] * (tot * (1.0f / D_)) + gb[0];
        gate[row] = 1.0f / (1.0f + expf(-z));
    }
}

// ============================================================
// weight transpose + fp16: dst[n][k] = h(src[k][n]); z selects weight
// ============================================================
__global__ __launch_bounds__(256) void wt_pre(const float* __restrict__ w0,
                                              const float* __restrict__ w1,
                                              const float* __restrict__ w2,
                                              const float* __restrict__ w3,
                                              __half* __restrict__ o0,
                                              __half* __restrict__ o1,
                                              __half* __restrict__ o2,
                                              __half* __restrict__ o3)
{
    __shared__ float t[32][33];
    const float* src = (blockIdx.z == 0) ? w0 : (blockIdx.z == 1) ? w1 : (blockIdx.z == 2) ? w2 : w3;
    __half*      dst = (blockIdx.z == 0) ? o0 : (blockIdx.z == 1) ? o1 : (blockIdx.z == 2) ? o2 : o3;
    int k0 = blockIdx.y * 32, n0 = blockIdx.x * 32;
    int tx = threadIdx.x & 31, ty = threadIdx.x >> 5;
    #pragma unroll
    for (int r = 0; r < 4; r++)
        t[ty + 8 * r][tx] = src[(size_t)(k0 + ty + 8 * r) * D_ + n0 + tx];
    __syncthreads();
    #pragma unroll
    for (int r = 0; r < 4; r++)
        dst[(size_t)(n0 + ty + 8 * r) * D_ + k0 + tx] = __float2half_rn(t[tx][ty + 8 * r]);
}

// ============================================================
// fp16 GEMM body: C[M,1024] = A @ Wt^T + bias
// 128x128 tile, BK=64, 256 thr (8 warps 2x4), ldmatrix fragments,
// cp.async double-buffered. mode: 0=float out, 1=half out, 2=half Vt out.
// dyn smem: 4 stages-of-operand * 128*72 halves = 73728 B
// ============================================================
#define GLD 72
#define GST (128 * GLD)     // halves per operand-stage

__device__ __forceinline__ void gemm_body(const __half* __restrict__ A,
                                          const __half* __restrict__ Wt,
                                          const float* __restrict__ bias,
                                          void* __restrict__ Cout,
                                          int mode, __half* smh,
                                          int m0, int n0)
{
    __half* Ast = smh;                   // 2 stages
    __half* Bst = smh + 2 * GST;         // 2 stages
    uint32_t sA = (uint32_t)__cvta_generic_to_shared(Ast);
    uint32_t sB = (uint32_t)__cvta_generic_to_shared(Bst);

    const int tid  = threadIdx.x;
    const int lane = tid & 31;
    const int warp = tid >> 5;
    const int wm = warp & 1;
    const int wn = warp >> 1;
    const int g  = lane >> 2;
    const int t4 = lane & 3;

    // cp geometry: 128 rows x 8 chunks(16B) per operand-stage, 4/thread
    const int crow = tid >> 3;          // plus i*32
    const int cch  = (tid & 7) * 8;     // half offset

    float4 acc[4][4];
    #pragma unroll
    for (int mt = 0; mt < 4; mt++)
        #pragma unroll
        for (int nt = 0; nt < 4; nt++)
            acc[mt][nt] = make_float4(0.f, 0.f, 0.f, 0.f);

    // prologue: k-tile 0 -> stage 0
    #pragma unroll
    for (int i = 0; i < 4; i++) {
        int row = crow + i * 32;
        cp16(sA + (row * GLD + cch) * 2, &A[(size_t)(m0 + row) * D_ + cch]);
        cp16(sB + (row * GLD + cch) * 2, &Wt[(size_t)(n0 + row) * D_ + cch]);
    }
    CP_COMMIT();

    // ldmatrix per-lane base offsets (halves)
    const int lrow8 = ((lane >> 3) & 1) * 8 + (lane & 7);   // row within 16
    const int lkhi  = (lane >> 4) * 8;                      // k-high selector
    const uint32_t aOff = ((wm * 64 + lrow8) * GLD + lkhi) * 2;
    const uint32_t bOff = ((wn * 32 + lrow8) * GLD + lkhi) * 2;

    for (int it = 0; it < 16; it++) {
        const int cur = it & 1;
        const int nxt = cur ^ 1;
        if (it + 1 < 16) {
            const int k0 = (it + 1) * 64;
            #pragma unroll
            for (int i = 0; i < 4; i++) {
                int row = crow + i * 32;
                cp16(sA + (nxt * GST + row * GLD + cch) * 2, &A[(size_t)(m0 + row) * D_ + k0 + cch]);
                cp16(sB + (nxt * GST + row * GLD + cch) * 2, &Wt[(size_t)(n0 + row) * D_ + k0 + cch]);
            }
        }
        CP_COMMIT();
        CP_WAIT1();
        __syncthreads();

        const uint32_t aB = sA + cur * GST * 2 + aOff;
        const uint32_t bB = sB + cur * GST * 2 + bOff;
        #pragma unroll
        for (int ks = 0; ks < 4; ks++) {
            uint32_t bf[4][2];
            #pragma unroll
            for (int p = 0; p < 2; p++) {
                uint32_t r0, r1, r2, r3;
                ldm4(r0, r1, r2, r3, bB + (p * 16 * GLD + ks * 16) * 2);
                bf[2 * p][0] = r0; bf[2 * p + 1][0] = r1;
                bf[2 * p][1] = r2; bf[2 * p + 1][1] = r3;
            }
            #pragma unroll
            for (int mt = 0; mt < 4; mt++) {
                uint32_t af[4];
                ldm4(af[0], af[1], af[2], af[3], aB + (mt * 16 * GLD + ks * 16) * 2);
                #pragma unroll
                for (int nt = 0; nt < 4; nt++)
                    mma_f16(acc[mt][nt], af, bf[nt][0], bf[nt][1]);
            }
        }
        __syncthreads();
    }

    if (mode == 0) {
        float* C = (float*)Cout;
        #pragma unroll
        for (int nt = 0; nt < 4; nt++) {
            int col = n0 + wn * 32 + nt * 8 + t4 * 2;
            float2 bb = *(const float2*)&bias[col];
            #pragma unroll
            for (int mt = 0; mt < 4; mt++) {
                int row = m0 + wm * 64 + mt * 16 + g;
                float2 o;
                o.x = acc[mt][nt].x + bb.x; o.y = acc[mt][nt].y + bb.y;
                *(float2*)&C[(size_t)row * D_ + col] = o;
                o.x = acc[mt][nt].z + bb.x; o.y = acc[mt][nt].w + bb.y;
                *(float2*)&C[(size_t)(row + 8) * D_ + col] = o;
            }
        }
    } else if (mode == 1) {
        __half* C = (__half*)Cout;
        #pragma unroll
        for (int nt = 0; nt < 4; nt++) {
            int col = n0 + wn * 32 + nt * 8 + t4 * 2;
            float2 bb = *(const float2*)&bias[col];
            #pragma unroll
            for (int mt = 0; mt < 4; mt++) {
                int row = m0 + wm * 64 + mt * 16 + g;
                *(__half2*)&C[(size_t)row * D_ + col] =
                    __floats2half2_rn(acc[mt][nt].x + bb.x, acc[mt][nt].y + bb.y);
                *(__half2*)&C[(size_t)(row + 8) * D_ + col] =
                    __floats2half2_rn(acc[mt][nt].z + bb.x, acc[mt][nt].w + bb.y);
            }
        }
    } else {
        // mode 2: transpose via smem, write Vt[b][n0+col][s]
        __syncthreads();
        __half* T = smh;   // [128 cols][144 rows pad] = 36864 halves
        #pragma unroll
        for (int nt = 0; nt < 4; nt++) {
            int col = wn * 32 + nt * 8 + 2 * t4;
            float2 bb = *(const float2*)&bias[n0 + col];
            #pragma unroll
            for (int mt = 0; mt < 4; mt++) {
                int row = wm * 64 + mt * 16 + g;
                T[col * 144 + row]           = __float2half_rn(acc[mt][nt].x + bb.x);
                T[(col + 1) * 144 + row]     = __float2half_rn(acc[mt][nt].y + bb.y);
                T[col * 144 + row + 8]       = __float2half_rn(acc[mt][nt].z + bb.x);
                T[(col + 1) * 144 + row + 8] = __float2half_rn(acc[mt][nt].w + bb.y);
            }
        }
        __syncthreads();
        __half* Vt = (__half*)Cout;
        int colc  = tid >> 1;
        int roff  = (tid & 1) * 64;
        int bb2   = m0 >> 11;             // batch
        int ms    = (m0 & (S_ - 1)) + roff;
        const uint4* src = (const uint4*)&T[colc * 144 + roff];
        uint4* dst = (uint4*)(Vt + ((size_t)bb2 * D_ + n0 + colc) * S_ + ms);
        #pragma unroll
        for (int i = 0; i < 8; i++) dst[i] = src[i];
    }
}

// fused Q/K/V projection: blockIdx.z selects weight/output/mode
__global__ __launch_bounds__(256) void gemm_qkv(const __half* __restrict__ A,
                                                const float* __restrict__ bq,
                                                const float* __restrict__ bk,
                                                const float* __restrict__ bv)
{
    extern __shared__ __half smh[];
    const int m0 = blockIdx.y * 128;
    const int n0 = blockIdx.x * 128;
    if (blockIdx.z == 0)      gemm_body(A, g_wqt, bq, g_qh, 1, smh, m0, n0);
    else if (blockIdx.z == 1) gemm_body(A, g_wkt, bk, g_kh, 1, smh, m0, n0);
    else                      gemm_body(A, g_wvt, bv, g_vt, 2, smh, m0, n0);
}

__global__ __launch_bounds__(256) void gemm_o(const __half* __restrict__ A,
                                              const float* __restrict__ bo,
                                              float* __restrict__ out)
{
    extern __shared__ __half smh[];
    gemm_body(A, g_wot, bo, out, 0, smh, blockIdx.y * 128, blockIdx.x * 128);
}

// ============================================================
// fp16 flash attention: ldmatrix fragments, P kept in registers.
// Block = 128 thr (4 warps) = 64-query tile of one (b,h).
// dyn smem: 4 * 64*72 halves = 36864 B
// ============================================================
#define SC_ (0.125f * 1.44269504f)   // 1/sqrt(64) * log2(e)
#define AH_ST (64 * 72)              // halves per stage

__global__ __launch_bounds__(128) void attn_h(const __half* __restrict__ q,
                                              const __half* __restrict__ k,
                                              const __half* __restrict__ vt,
                                              const float* __restrict__ gate,
                                              __half* __restrict__ ctx)
{
    extern __shared__ __half smh[];
    __half* Kst = smh;                 // 2 stages [64 key][72]
    __half* Vst = smh + 2 * AH_ST;     // 2 stages [64 d][72 key]
    uint32_t sK = (uint32_t)__cvta_generic_to_shared(Kst);
    uint32_t sV = (uint32_t)__cvta_generic_to_shared(Vst);

    const int b  = blockIdx.z;
    const int h  = blockIdx.y;
    const int q0 = blockIdx.x * 64;
    const int tid  = threadIdx.x;
    const int lane = tid & 31;
    const int w    = tid >> 5;
    const int g  = lane >> 2;
    const int t4 = lane & 3;
    const int wrow = w * 16;

    // ---- stage Q tile through Kst stage0, pull fragments ----
    #pragma unroll
    for (int i = 0; i < 4; i++) {
        int e = tid + i * 128;
        int row = e >> 3, ch = (e & 7) * 8;
        *(uint4*)&Kst[row * 72 + ch] =
            *(const uint4*)(q + ((size_t)(b * S_ + q0 + row)) * D_ + h * DH_ + ch);
    }
    __syncthreads();
    uint32_t aq[4][4];
    {
        const int lrow8 = ((lane >> 3) & 1) * 8 + (lane & 7);
        const int lkhi  = (lane >> 4) * 8;
        uint32_t qB = sK + ((wrow + lrow8) * 72 + lkhi) * 2;
        #pragma unroll
        for (int ks = 0; ks < 4; ks++)
            ldm4(aq[ks][0], aq[ks][1], aq[ks][2], aq[ks][3], qB + ks * 32);
    }
    __syncthreads();

    float4 accO[8];
    #pragma unroll
    for (int nt = 0; nt < 8; nt++) accO[nt] = make_float4(0.f, 0.f, 0.f, 0.f);
    float mxlo = -1e30f, mxhi = -1e30f, llo = 0.f, lhi = 0.f;

    const int crow = tid >> 3;          // 0..15, 4 passes -> 64 rows
    const int cch  = (tid & 7) * 8;

    const __half* kbase  = k  + ((size_t)b * S_) * D_ + h * DH_;
    const __half* vtbase = vt + ((size_t)b * D_ + h * DH_) * S_;

    // prologue: chunk 0 -> stage 0
    #pragma unroll
    for (int i = 0; i < 4; i++) {
        int row = crow + i * 16;
        cp16(sK + (row * 72 + cch) * 2, kbase + (size_t)row * D_ + cch);
        cp16(sV + (row * 72 + cch) * 2, vtbase + (size_t)row * S_ + cch);
    }
    CP_COMMIT();

    // per-lane ldmatrix base offset within a stage (halves)
    const int lrow8 = ((lane >> 3) & 1) * 8 + (lane & 7);
    const int lkhi  = (lane >> 4) * 8;
    const uint32_t fOff = (lrow8 * 72 + lkhi) * 2;

    for (int c = 0; c < S_ / 64; c++) {
        const int cur = c & 1;
        const int nxt = cur ^ 1;
        if (c + 1 < S_ / 64) {
            const int kc = (c + 1) * 64;
            #pragma unroll
            for (int i = 0; i < 4; i++) {
                int row = crow + i * 16;
                cp16(sK + (nxt * AH_ST + row * 72 + cch) * 2, kbase + (size_t)(kc + row) * D_ + cch);
                cp16(sV + (nxt * AH_ST + row * 72 + cch) * 2, vtbase + (size_t)row * S_ + kc + cch);
            }
        }
        CP_COMMIT();
        CP_WAIT1();
        __syncthreads();

        const uint32_t kB = sK + cur * AH_ST * 2 + fOff;
        const uint32_t vB = sV + cur * AH_ST * 2 + fOff;

        // ---- scores = Q @ K^T (ldmatrix B-frags from K [key][d]) ----
        float4 s[8];
        #pragma unroll
        for (int nt = 0; nt < 8; nt++) s[nt] = make_float4(0.f, 0.f, 0.f, 0.f);
        #pragma unroll
        for (int ks = 0; ks < 4; ks++) {
            #pragma unroll
            for (int p = 0; p < 4; p++) {
                uint32_t r0, r1, r2, r3;
                ldm4(r0, r1, r2, r3, kB + (p * 16 * 72 + ks * 16) * 2);
                mma_f16(s[2 * p],     aq[ks], r0, r2);
                mma_f16(s[2 * p + 1], aq[ks], r1, r3);
            }
        }

        // ---- online softmax ----
        float mlo = -1e30f, mhi = -1e30f;
        #pragma unroll
        for (int nt = 0; nt < 8; nt++) {
            mlo = fmaxf(mlo, fmaxf(s[nt].x, s[nt].y));
            mhi = fmaxf(mhi, fmaxf(s[nt].z, s[nt].w));
        }
        mlo = fmaxf(mlo, __shfl_xor_sync(0xffffffffu, mlo, 1));
        mlo = fmaxf(mlo, __shfl_xor_sync(0xffffffffu, mlo, 2));
        mhi = fmaxf(mhi, __shfl_xor_sync(0xffffffffu, mhi, 1));
        mhi = fmaxf(mhi, __shfl_xor_sync(0xffffffffu, mhi, 2));

        float mnlo = fmaxf(mxlo, mlo);
        float mnhi = fmaxf(mxhi, mhi);
        float clo = exp2f((mxlo - mnlo) * SC_);
        float chi = exp2f((mxhi - mnhi) * SC_);

        float slo = 0.f, shi = 0.f;
        #pragma unroll
        for (int nt = 0; nt < 8; nt++) {
            s[nt].x = exp2f((s[nt].x - mnlo) * SC_);
            s[nt].y = exp2f((s[nt].y - mnlo) * SC_);
            s[nt].z = exp2f((s[nt].z - mnhi) * SC_);
            s[nt].w = exp2f((s[nt].w - mnhi) * SC_);
            slo += s[nt].x + s[nt].y;
            shi += s[nt].z + s[nt].w;
        }
        slo += __shfl_xor_sync(0xffffffffu, slo, 1);
        slo += __shfl_xor_sync(0xffffffffu, slo, 2);
        shi += __shfl_xor_sync(0xffffffffu, shi, 1);
        shi += __shfl_xor_sync(0xffffffffu, shi, 2);
        llo = llo * clo + slo;
        lhi = lhi * chi + shi;
        mxlo = mnlo; mxhi = mnhi;

        #pragma unroll
        for (int nt = 0; nt < 8; nt++) {
            accO[nt].x *= clo; accO[nt].y *= clo;
            accO[nt].z *= chi; accO[nt].w *= chi;
        }

        // ---- O += P @ V : P fragments built directly from s registers ----
        #pragma unroll
        for (int ks = 0; ks < 4; ks++) {
            uint32_t ap[4];
            ap[0] = f2h2(s[2 * ks].x,     s[2 * ks].y);
            ap[1] = f2h2(s[2 * ks].z,     s[2 * ks].w);
            ap[2] = f2h2(s[2 * ks + 1].x, s[2 * ks + 1].y);
            ap[3] = f2h2(s[2 * ks + 1].z, s[2 * ks + 1].w);
            #pragma unroll
            for (int p = 0; p < 4; p++) {
                uint32_t r0, r1, r2, r3;
                ldm4(r0, r1, r2, r3, vB + (p * 16 * 72 + ks * 16) * 2);
                mma_f16(accO[2 * p],     ap, r0, r2);
                mma_f16(accO[2 * p + 1], ap, r1, r3);
            }
        }
        __syncthreads();   // stage reads done before it becomes a prefetch target
    }

    // ---- epilogue: gate/l scale, fp16 store (feeds Wo GEMM) ----
    int qlo = q0 + wrow + g;
    int qhi = qlo + 8;
    float glo = gate[b * S_ + qlo] / llo;
    float ghi = gate[b * S_ + qhi] / lhi;
    #pragma unroll
    for (int nt = 0; nt < 8; nt++) {
        int col = h * DH_ + nt * 8 + 2 * t4;
        *(__half2*)&ctx[((size_t)(b * S_ + qlo)) * D_ + col] =
            __floats2half2_rn(accO[nt].x * glo, accO[nt].y * glo);
        *(__half2*)&ctx[((size_t)(b * S_ + qhi)) * D_ + col] =
            __floats2half2_rn(accO[nt].z * ghi, accO[nt].w * ghi);
    }
}

// ============================================================
// Launch
// ============================================================
extern "C" void kernel_launch(void* const* d_in, const int* in_sizes, int n_in,
                              void* d_out, int out_size)
{
    const float* hs = (const float*)d_in[0];
    const float* Wq = (const float*)d_in[1];
    const float* bq = (const float*)d_in[2];
    const float* Wk = (const float*)d_in[3];
    const float* bk = (const float*)d_in[4];
    const float* Wv = (const float*)d_in[5];
    const float* bv = (const float*)d_in[6];
    const float* Wo = (const float*)d_in[7];
    const float* bo = (const float*)d_in[8];
    const float* gf = (const float*)d_in[9];
    const float* gb = (const float*)d_in[10];
    float* out = (float*)d_out;

    __half *hsh, *qh, *kh, *vtp, *ch, *wq, *wk, *wv, *wo;
    float *gp;
    cudaGetSymbolAddress((void**)&hsh, g_hsh);
    cudaGetSymbolAddress((void**)&qh, g_qh);
    cudaGetSymbolAddress((void**)&kh, g_kh);
    cudaGetSymbolAddress((void**)&vtp, g_vt);
    cudaGetSymbolAddress((void**)&ch, g_ch);
    cudaGetSymbolAddress((void**)&gp, g_gate);
    cudaGetSymbolAddress((void**)&wq, g_wqt);
    cudaGetSymbolAddress((void**)&wk, g_wkt);
    cudaGetSymbolAddress((void**)&wv, g_wvt);
    cudaGetSymbolAddress((void**)&wo, g_wot);

    const int SMEM_G = 73728;
    const int SMEM_A = 36864;
    cudaFuncSetAttribute(gemm_qkv, cudaFuncAttributeMaxDynamicSharedMemorySize, SMEM_G);
    cudaFuncSetAttribute(gemm_o,   cudaFuncAttributeMaxDynamicSharedMemorySize, SMEM_G);
    cudaFuncSetAttribute(attn_h,   cudaFuncAttributeMaxDynamicSharedMemorySize, SMEM_A);

    hs_pre<<<M_, 256>>>(hs, hsh, gf, gb, gp);
    wt_pre<<<dim3(32, 32, 4), 256>>>(Wq, Wk, Wv, Wo, wq, wk, wv, wo);

    gemm_qkv<<<dim3(D_ / 128, M_ / 128, 3), 256, SMEM_G>>>(hsh, bq, bk, bv);
    attn_h<<<dim3(S_ / 64, H_, B_), 128, SMEM_A>>>(qh, kh, vtp, gp, ch);
    gemm_o<<<dim3(D_ / 128, M_ / 128), 256, SMEM_G>>>(ch, bo, out);
}

// round 8
// speedup vs baseline: 8.6047x; 1.0757x over previous
#include <cuda_runtime.h>
#include <cuda_fp16.h>
#include <math.h>
#include <stdint.h>

#define B_ 2
#define S_ 2048
#define D_ 1024
#define H_ 16
#define DH_ 64
#define M_ (B_ * S_)   // 4096 token rows

#define SC_ (0.125f * 1.44269504f)   // 1/sqrt(64) * log2(e), folded into Wq/bq

// -------- scratch (allocation-free: __device__ globals) --------
__device__ __half g_hsh[M_ * D_];   // fp16 hidden_states
__device__ __half g_qh[M_ * D_];    // Q pre-scaled by SC_
__device__ __half g_kh[M_ * D_];
__device__ __half g_vt[M_ * D_];    // V transposed: [b][d_model][s]
__device__ __half g_ch[M_ * D_];    // ctx fp16
__device__ float  g_gate[M_];
__device__ __half g_wqt[D_ * D_];   // fp16, transposed weights [n][k] (Wq pre-scaled)
__device__ __half g_wkt[D_ * D_];
__device__ __half g_wvt[D_ * D_];
__device__ __half g_wot[D_ * D_];

// ============================================================
// helpers
// ============================================================
__device__ __forceinline__ void mma_f16(float4& d, const uint32_t a[4], uint32_t b0, uint32_t b1) {
    asm volatile(
        "mma.sync.aligned.m16n8k16.row.col.f32.f16.f16.f32 "
        "{%0,%1,%2,%3}, {%4,%5,%6,%7}, {%8,%9}, {%0,%1,%2,%3};"
        : "+f"(d.x), "+f"(d.y), "+f"(d.z), "+f"(d.w)
        : "r"(a[0]), "r"(a[1]), "r"(a[2]), "r"(a[3]), "r"(b0), "r"(b1));
}
__device__ __forceinline__ void ldm4(uint32_t& r0, uint32_t& r1, uint32_t& r2, uint32_t& r3,
                                     uint32_t addr) {
    asm volatile("ldmatrix.sync.aligned.m8n8.x4.shared.b16 {%0,%1,%2,%3}, [%4];"
                 : "=r"(r0), "=r"(r1), "=r"(r2), "=r"(r3) : "r"(addr));
}
__device__ __forceinline__ void cp16(uint32_t saddr, const void* gptr) {
    asm volatile("cp.async.cg.shared.global [%0], [%1], 16;" :: "r"(saddr), "l"(gptr));
}
#define CP_COMMIT() asm volatile("cp.async.commit_group;")
#define CP_WAIT1()  asm volatile("cp.async.wait_group 1;")

__device__ __forceinline__ uint32_t f2h2(float a, float b) {
    __half2 h = __floats2half2_rn(a, b);
    return *(uint32_t*)&h;
}
__device__ __forceinline__ uint32_t hmax2u(uint32_t a, uint32_t b) {
    __half2 r = __hmax2(*(__half2*)&a, *(__half2*)&b);
    return *(uint32_t*)&r;
}
__device__ __forceinline__ uint32_t hsub2u(uint32_t a, uint32_t b) {
    __half2 r = __hsub2(*(__half2*)&a, *(__half2*)&b);
    return *(uint32_t*)&r;
}
__device__ __forceinline__ uint32_t ex2u(uint32_t a) {
    uint32_t d;
    asm("ex2.approx.f16x2 %0, %1;" : "=r"(d) : "r"(a));
    return d;
}
#define ONES_H2 0x3C003C00u

// ============================================================
// hs -> fp16 + gating (one pass)
// ============================================================
__global__ __launch_bounds__(256) void hs_pre(const float* __restrict__ hs,
                                              __half* __restrict__ hsh,
                                              const float* __restrict__ gf,
                                              const float* __restrict__ gb,
                                              float* __restrict__ gate)
{
    __shared__ float red[8];
    int row = blockIdx.x;
    int t = threadIdx.x;
    float4 v = *(const float4*)(hs + (size_t)row * D_ + t * 4);
    float s = (v.x + v.y) + (v.z + v.w);
    __half2* dst = (__half2*)(hsh + (size_t)row * D_ + t * 4);
    dst[0] = __floats2half2_rn(v.x, v.y);
    dst[1] = __floats2half2_rn(v.z, v.w);
    #pragma unroll
    for (int st = 16; st > 0; st >>= 1) s += __shfl_xor_sync(0xffffffffu, s, st);
    if ((t & 31) == 0) red[t >> 5] = s;
    __syncthreads();
    if (t == 0) {
        float tot = 0.f;
        #pragma unroll
        for (int i = 0; i < 8; i++) tot += red[i];
        float z = gf[0] * (tot * (1.0f / D_)) + gb[0];
        gate[row] = 1.0f / (1.0f + expf(-z));
    }
}

// ============================================================
// weight transpose + fp16: dst[n][k] = h(scale * src[k][n])
// z=0 (Wq) gets scale SC_ folded in (fp32).
// ============================================================
__global__ __launch_bounds__(256) void wt_pre(const float* __restrict__ w0,
                                              const float* __restrict__ w1,
                                              const float* __restrict__ w2,
                                              const float* __restrict__ w3,
                                              __half* __restrict__ o0,
                                              __half* __restrict__ o1,
                                              __half* __restrict__ o2,
                                              __half* __restrict__ o3)
{
    __shared__ float t[32][33];
    const float* src = (blockIdx.z == 0) ? w0 : (blockIdx.z == 1) ? w1 : (blockIdx.z == 2) ? w2 : w3;
    __half*      dst = (blockIdx.z == 0) ? o0 : (blockIdx.z == 1) ? o1 : (blockIdx.z == 2) ? o2 : o3;
    const float scale = (blockIdx.z == 0) ? SC_ : 1.0f;
    int k0 = blockIdx.y * 32, n0 = blockIdx.x * 32;
    int tx = threadIdx.x & 31, ty = threadIdx.x >> 5;
    #pragma unroll
    for (int r = 0; r < 4; r++)
        t[ty + 8 * r][tx] = src[(size_t)(k0 + ty + 8 * r) * D_ + n0 + tx];
    __syncthreads();
    #pragma unroll
    for (int r = 0; r < 4; r++)
        dst[(size_t)(n0 + ty + 8 * r) * D_ + k0 + tx] = __float2half_rn(scale * t[tx][ty + 8 * r]);
}

// ============================================================
// fp16 GEMM body (R7-proven): C = A @ Wt^T + bscale*bias
// 128x128 tile, BK=64, 256 thr, ldmatrix, cp.async double-buffered.
// mode: 0=float out, 1=half out, 2=half Vt out.
// ============================================================
#define GLD 72
#define GST (128 * GLD)

__device__ __forceinline__ void gemm_body(const __half* __restrict__ A,
                                          const __half* __restrict__ Wt,
                                          const float* __restrict__ bias,
                                          void* __restrict__ Cout,
                                          int mode, __half* smh,
                                          int m0, int n0, float bscale)
{
    __half* Ast = smh;
    __half* Bst = smh + 2 * GST;
    uint32_t sA = (uint32_t)__cvta_generic_to_shared(Ast);
    uint32_t sB = (uint32_t)__cvta_generic_to_shared(Bst);

    const int tid  = threadIdx.x;
    const int lane = tid & 31;
    const int warp = tid >> 5;
    const int wm = warp & 1;
    const int wn = warp >> 1;
    const int g  = lane >> 2;
    const int t4 = lane & 3;

    const int crow = tid >> 3;
    const int cch  = (tid & 7) * 8;

    float4 acc[4][4];
    #pragma unroll
    for (int mt = 0; mt < 4; mt++)
        #pragma unroll
        for (int nt = 0; nt < 4; nt++)
            acc[mt][nt] = make_float4(0.f, 0.f, 0.f, 0.f);

    #pragma unroll
    for (int i = 0; i < 4; i++) {
        int row = crow + i * 32;
        cp16(sA + (row * GLD + cch) * 2, &A[(size_t)(m0 + row) * D_ + cch]);
        cp16(sB + (row * GLD + cch) * 2, &Wt[(size_t)(n0 + row) * D_ + cch]);
    }
    CP_COMMIT();

    const int lrow8 = ((lane >> 3) & 1) * 8 + (lane & 7);
    const int lkhi  = (lane >> 4) * 8;
    const uint32_t aOff = ((wm * 64 + lrow8) * GLD + lkhi) * 2;
    const uint32_t bOff = ((wn * 32 + lrow8) * GLD + lkhi) * 2;

    for (int it = 0; it < 16; it++) {
        const int cur = it & 1;
        const int nxt = cur ^ 1;
        if (it + 1 < 16) {
            const int k0 = (it + 1) * 64;
            #pragma unroll
            for (int i = 0; i < 4; i++) {
                int row = crow + i * 32;
                cp16(sA + (nxt * GST + row * GLD + cch) * 2, &A[(size_t)(m0 + row) * D_ + k0 + cch]);
                cp16(sB + (nxt * GST + row * GLD + cch) * 2, &Wt[(size_t)(n0 + row) * D_ + k0 + cch]);
            }
        }
        CP_COMMIT();
        CP_WAIT1();
        __syncthreads();

        const uint32_t aB = sA + cur * GST * 2 + aOff;
        const uint32_t bB = sB + cur * GST * 2 + bOff;
        #pragma unroll
        for (int ks = 0; ks < 4; ks++) {
            uint32_t bf[4][2];
            #pragma unroll
            for (int p = 0; p < 2; p++) {
                uint32_t r0, r1, r2, r3;
                ldm4(r0, r1, r2, r3, bB + (p * 16 * GLD + ks * 16) * 2);
                bf[2 * p][0] = r0; bf[2 * p + 1][0] = r1;
                bf[2 * p][1] = r2; bf[2 * p + 1][1] = r3;
            }
            #pragma unroll
            for (int mt = 0; mt < 4; mt++) {
                uint32_t af[4];
                ldm4(af[0], af[1], af[2], af[3], aB + (mt * 16 * GLD + ks * 16) * 2);
                #pragma unroll
                for (int nt = 0; nt < 4; nt++)
                    mma_f16(acc[mt][nt], af, bf[nt][0], bf[nt][1]);
            }
        }
        __syncthreads();
    }

    if (mode == 0) {
        float* C = (float*)Cout;
        #pragma unroll
        for (int nt = 0; nt < 4; nt++) {
            int col = n0 + wn * 32 + nt * 8 + t4 * 2;
            float2 bb = *(const float2*)&bias[col];
            bb.x *= bscale; bb.y *= bscale;
            #pragma unroll
            for (int mt = 0; mt < 4; mt++) {
                int row = m0 + wm * 64 + mt * 16 + g;
                float2 o;
                o.x = acc[mt][nt].x + bb.x; o.y = acc[mt][nt].y + bb.y;
                *(float2*)&C[(size_t)row * D_ + col] = o;
                o.x = acc[mt][nt].z + bb.x; o.y = acc[mt][nt].w + bb.y;
                *(float2*)&C[(size_t)(row + 8) * D_ + col] = o;
            }
        }
    } else if (mode == 1) {
        __half* C = (__half*)Cout;
        #pragma unroll
        for (int nt = 0; nt < 4; nt++) {
            int col = n0 + wn * 32 + nt * 8 + t4 * 2;
            float2 bb = *(const float2*)&bias[col];
            bb.x *= bscale; bb.y *= bscale;
            #pragma unroll
            for (int mt = 0; mt < 4; mt++) {
                int row = m0 + wm * 64 + mt * 16 + g;
                *(__half2*)&C[(size_t)row * D_ + col] =
                    __floats2half2_rn(acc[mt][nt].x + bb.x, acc[mt][nt].y + bb.y);
                *(__half2*)&C[(size_t)(row + 8) * D_ + col] =
                    __floats2half2_rn(acc[mt][nt].z + bb.x, acc[mt][nt].w + bb.y);
            }
        }
    } else {
        __syncthreads();
        __half* T = smh;   // [128 cols][144 rows pad]
        #pragma unroll
        for (int nt = 0; nt < 4; nt++) {
            int col = wn * 32 + nt * 8 + 2 * t4;
            float2 bb = *(const float2*)&bias[n0 + col];
            #pragma unroll
            for (int mt = 0; mt < 4; mt++) {
                int row = wm * 64 + mt * 16 + g;
                T[col * 144 + row]           = __float2half_rn(acc[mt][nt].x + bb.x);
                T[(col + 1) * 144 + row]     = __float2half_rn(acc[mt][nt].y + bb.y);
                T[col * 144 + row + 8]       = __float2half_rn(acc[mt][nt].z + bb.x);
                T[(col + 1) * 144 + row + 8] = __float2half_rn(acc[mt][nt].w + bb.y);
            }
        }
        __syncthreads();
        __half* Vt = (__half*)Cout;
        int colc  = tid >> 1;
        int roff  = (tid & 1) * 64;
        int bb2   = m0 >> 11;
        int ms    = (m0 & (S_ - 1)) + roff;
        const uint4* src = (const uint4*)&T[colc * 144 + roff];
        uint4* dst = (uint4*)(Vt + ((size_t)bb2 * D_ + n0 + colc) * S_ + ms);
        #pragma unroll
        for (int i = 0; i < 8; i++) dst[i] = src[i];
    }
}

__global__ __launch_bounds__(256) void gemm_qkv(const __half* __restrict__ A,
                                                const float* __restrict__ bq,
                                                const float* __restrict__ bk,
                                                const float* __restrict__ bv)
{
    extern __shared__ __half smh[];
    const int m0 = blockIdx.y * 128;
    const int n0 = blockIdx.x * 128;
    if (blockIdx.z == 0)      gemm_body(A, g_wqt, bq, g_qh, 1, smh, m0, n0, SC_);
    else if (blockIdx.z == 1) gemm_body(A, g_wkt, bk, g_kh, 1, smh, m0, n0, 1.0f);
    else                      gemm_body(A, g_wvt, bv, g_vt, 2, smh, m0, n0, 1.0f);
}

__global__ __launch_bounds__(256) void gemm_o(const __half* __restrict__ A,
                                              const float* __restrict__ bo,
                                              float* __restrict__ out)
{
    extern __shared__ __half smh[];
    gemm_body(A, g_wot, bo, out, 0, smh, blockIdx.y * 128, blockIdx.x * 128, 1.0f);
}

// ============================================================
// fp16 flash attention, fp16 softmax pipeline + ones-MMA rowsums.
// Scores arrive pre-scaled (SC_ folded into Wq/bq) = log2-domain.
// Block = 128 thr (4 warps) = 64-query tile of one (b,h).
// dyn smem: 4 * 64*72 halves = 36864 B
// ============================================================
#define AH_ST (64 * 72)

__global__ __launch_bounds__(128) void attn_h(const __half* __restrict__ q,
                                              const __half* __restrict__ k,
                                              const __half* __restrict__ vt,
                                              const float* __restrict__ gate,
                                              __half* __restrict__ ctx)
{
    extern __shared__ __half smh[];
    __half* Kst = smh;
    __half* Vst = smh + 2 * AH_ST;
    uint32_t sK = (uint32_t)__cvta_generic_to_shared(Kst);
    uint32_t sV = (uint32_t)__cvta_generic_to_shared(Vst);

    const int b  = blockIdx.z;
    const int h  = blockIdx.y;
    const int q0 = blockIdx.x * 64;
    const int tid  = threadIdx.x;
    const int lane = tid & 31;
    const int w    = tid >> 5;
    const int g  = lane >> 2;
    const int t4 = lane & 3;
    const int wrow = w * 16;

    // ---- stage Q tile through Kst stage0, pull fragments ----
    #pragma unroll
    for (int i = 0; i < 4; i++) {
        int e = tid + i * 128;
        int row = e >> 3, ch = (e & 7) * 8;
        *(uint4*)&Kst[row * 72 + ch] =
            *(const uint4*)(q + ((size_t)(b * S_ + q0 + row)) * D_ + h * DH_ + ch);
    }
    __syncthreads();
    uint32_t aq[4][4];
    {
        const int lr = ((lane >> 3) & 1) * 8 + (lane & 7);
        const int lk = (lane >> 4) * 8;
        uint32_t qB = sK + ((wrow + lr) * 72 + lk) * 2;
        #pragma unroll
        for (int ks = 0; ks < 4; ks++)
            ldm4(aq[ks][0], aq[ks][1], aq[ks][2], aq[ks][3], qB + ks * 32);
    }
    __syncthreads();

    float4 accO[8];
    #pragma unroll
    for (int nt = 0; nt < 8; nt++) accO[nt] = make_float4(0.f, 0.f, 0.f, 0.f);
    float llo = 0.f, lhi = 0.f;
    uint32_t mx2 = f2h2(-30000.f, -30000.f);   // running max (row g, row g+8)

    const int crow = tid >> 3;
    const int cch  = (tid & 7) * 8;

    const __half* kbase  = k  + ((size_t)b * S_) * D_ + h * DH_;
    const __half* vtbase = vt + ((size_t)b * D_ + h * DH_) * S_;

    #pragma unroll
    for (int i = 0; i < 4; i++) {
        int row = crow + i * 16;
        cp16(sK + (row * 72 + cch) * 2, kbase + (size_t)row * D_ + cch);
        cp16(sV + (row * 72 + cch) * 2, vtbase + (size_t)row * S_ + cch);
    }
    CP_COMMIT();

    const int lrow8 = ((lane >> 3) & 1) * 8 + (lane & 7);
    const int lkhi  = (lane >> 4) * 8;
    const uint32_t fOff = (lrow8 * 72 + lkhi) * 2;

    for (int c = 0; c < S_ / 64; c++) {
        const int cur = c & 1;
        const int nxt = cur ^ 1;
        if (c + 1 < S_ / 64) {
            const int kc = (c + 1) * 64;
            #pragma unroll
            for (int i = 0; i < 4; i++) {
                int row = crow + i * 16;
                cp16(sK + (nxt * AH_ST + row * 72 + cch) * 2, kbase + (size_t)(kc + row) * D_ + cch);
                cp16(sV + (nxt * AH_ST + row * 72 + cch) * 2, vtbase + (size_t)row * S_ + kc + cch);
            }
        }
        CP_COMMIT();
        CP_WAIT1();
        __syncthreads();

        const uint32_t kB = sK + cur * AH_ST * 2 + fOff;
        const uint32_t vB = sV + cur * AH_ST * 2 + fOff;

        // ---- scores = Q @ K^T (pre-scaled: log2-domain) ----
        float4 s[8];
        #pragma unroll
        for (int nt = 0; nt < 8; nt++) s[nt] = make_float4(0.f, 0.f, 0.f, 0.f);
        #pragma unroll
        for (int ks = 0; ks < 4; ks++) {
            #pragma unroll
            for (int p = 0; p < 4; p++) {
                uint32_t r0, r1, r2, r3;
                ldm4(r0, r1, r2, r3, kB + (p * 16 * 72 + ks * 16) * 2);
                mma_f16(s[2 * p],     aq[ks], r0, r2);
                mma_f16(s[2 * p + 1], aq[ks], r1, r3);
            }
        }

        // ---- fp16 softmax: pack, hmax2 tree, 2 shfl, ex2 ----
        uint32_t pl[8], ph[8];
        #pragma unroll
        for (int nt = 0; nt < 8; nt++) {
            pl[nt] = f2h2(s[nt].x, s[nt].y);   // row g
            ph[nt] = f2h2(s[nt].z, s[nt].w);   // row g+8
        }
        uint32_t mgu = pl[0], mhu = ph[0];
        #pragma unroll
        for (int nt = 1; nt < 8; nt++) { mgu = hmax2u(mgu, pl[nt]); mhu = hmax2u(mhu, ph[nt]); }
        __half2 mgh = *(__half2*)&mgu;
        __half2 mhh = *(__half2*)&mhu;
        __half2 mc = __halves2half2(__hmax(__low2half(mgh), __high2half(mgh)),
                                    __hmax(__low2half(mhh), __high2half(mhh)));
        uint32_t mcu = *(uint32_t*)&mc;
        mcu = hmax2u(mcu, __shfl_xor_sync(0xffffffffu, mcu, 1));
        mcu = hmax2u(mcu, __shfl_xor_sync(0xffffffffu, mcu, 2));
        uint32_t mn2 = hmax2u(mcu, mx2);

        uint32_t corr2 = ex2u(hsub2u(mx2, mn2));
        __half2 c2 = *(__half2*)&corr2;
        float clo = __low2float(c2);
        float chi = __high2float(c2);
        mx2 = mn2;

        __half2 mn2h = *(__half2*)&mn2;
        __half2 bg = __half2half2(__low2half(mn2h));
        __half2 bh = __half2half2(__high2half(mn2h));
        uint32_t bgu = *(uint32_t*)&bg;
        uint32_t bhu = *(uint32_t*)&bh;
        #pragma unroll
        for (int nt = 0; nt < 8; nt++) {
            pl[nt] = ex2u(hsub2u(pl[nt], bgu));   // P row g, fp16
            ph[nt] = ex2u(hsub2u(ph[nt], bhu));   // P row g+8
        }

        // ---- row sums via ones-MMA (fp32 accum; consistent with PV) ----
        float4 accS = make_float4(0.f, 0.f, 0.f, 0.f);
        #pragma unroll
        for (int ks = 0; ks < 4; ks++) {
            uint32_t ap[4] = {pl[2 * ks], ph[2 * ks], pl[2 * ks + 1], ph[2 * ks + 1]};
            mma_f16(accS, ap, ONES_H2, ONES_H2);
        }
        llo = llo * clo + accS.x;
        lhi = lhi * chi + accS.z;

        #pragma unroll
        for (int nt = 0; nt < 8; nt++) {
            accO[nt].x *= clo; accO[nt].y *= clo;
            accO[nt].z *= chi; accO[nt].w *= chi;
        }

        // ---- O += P @ V ----
        #pragma unroll
        for (int ks = 0; ks < 4; ks++) {
            uint32_t ap[4] = {pl[2 * ks], ph[2 * ks], pl[2 * ks + 1], ph[2 * ks + 1]};
            #pragma unroll
            for (int p = 0; p < 4; p++) {
                uint32_t r0, r1, r2, r3;
                ldm4(r0, r1, r2, r3, vB + (p * 16 * 72 + ks * 16) * 2);
                mma_f16(accO[2 * p],     ap, r0, r2);
                mma_f16(accO[2 * p + 1], ap, r1, r3);
            }
        }
        __syncthreads();
    }

    // ---- epilogue: gate/l scale, fp16 store ----
    int qlo = q0 + wrow + g;
    int qhi = qlo + 8;
    float glo = gate[b * S_ + qlo] / llo;
    float ghi = gate[b * S_ + qhi] / lhi;
    #pragma unroll
    for (int nt = 0; nt < 8; nt++) {
        int col = h * DH_ + nt * 8 + 2 * t4;
        *(__half2*)&ctx[((size_t)(b * S_ + qlo)) * D_ + col] =
            __floats2half2_rn(accO[nt].x * glo, accO[nt].y * glo);
        *(__half2*)&ctx[((size_t)(b * S_ + qhi)) * D_ + col] =
            __floats2half2_rn(accO[nt].z * ghi, accO[nt].w * ghi);
    }
}

// ============================================================
// Launch
// ============================================================
extern "C" void kernel_launch(void* const* d_in, const int* in_sizes, int n_in,
                              void* d_out, int out_size)
{
    const float* hs = (const float*)d_in[0];
    const float* Wq = (const float*)d_in[1];
    const float* bq = (const float*)d_in[2];
    const float* Wk = (const float*)d_in[3];
    const float* bk = (const float*)d_in[4];
    const float* Wv = (const float*)d_in[5];
    const float* bv = (const float*)d_in[6];
    const float* Wo = (const float*)d_in[7];
    const float* bo = (const float*)d_in[8];
    const float* gf = (const float*)d_in[9];
    const float* gb = (const float*)d_in[10];
    float* out = (float*)d_out;

    __half *hsh, *qh, *kh, *vtp, *ch;
    float *gp;
    cudaGetSymbolAddress((void**)&hsh, g_hsh);
    cudaGetSymbolAddress((void**)&qh, g_qh);
    cudaGetSymbolAddress((void**)&kh, g_kh);
    cudaGetSymbolAddress((void**)&vtp, g_vt);
    cudaGetSymbolAddress((void**)&ch, g_ch);
    cudaGetSymbolAddress((void**)&gp, g_gate);
    __half *wq, *wk, *wv, *wo;
    cudaGetSymbolAddress((void**)&wq, g_wqt);
    cudaGetSymbolAddress((void**)&wk, g_wkt);
    cudaGetSymbolAddress((void**)&wv, g_wvt);
    cudaGetSymbolAddress((void**)&wo, g_wot);

    const int SMEM_G = 73728;
    const int SMEM_A = 36864;
    cudaFuncSetAttribute(gemm_qkv, cudaFuncAttributeMaxDynamicSharedMemorySize, SMEM_G);
    cudaFuncSetAttribute(gemm_o,   cudaFuncAttributeMaxDynamicSharedMemorySize, SMEM_G);
    cudaFuncSetAttribute(attn_h,   cudaFuncAttributeMaxDynamicSharedMemorySize, SMEM_A);

    hs_pre<<<M_, 256>>>(hs, hsh, gf, gb, gp);
    wt_pre<<<dim3(32, 32, 4), 256>>>(Wq, Wk, Wv, Wo, wq, wk, wv, wo);

    gemm_qkv<<<dim3(D_ / 128, M_ / 128, 3), 256, SMEM_G>>>(hsh, bq, bk, bv);
    attn_h<<<dim3(S_ / 64, H_, B_), 128, SMEM_A>>>(qh, kh, vtp, gp, ch);
    gemm_o<<<dim3(D_ / 128, M_ / 128), 256, SMEM_G>>>(ch, bo, out);
}

// round 9
// speedup vs baseline: 8.7245x; 1.0139x over previous
#include <cuda_runtime.h>
#include <cuda_fp16.h>
#include <math.h>
#include <stdint.h>

#define B_ 2
#define S_ 2048
#define D_ 1024
#define H_ 16
#define DH_ 64
#define M_ (B_ * S_)   // 4096 token rows

#define SC_ (0.125f * 1.44269504f)   // 1/sqrt(64) * log2(e), folded into Wq/bq

// -------- scratch (allocation-free: __device__ globals) --------
__device__ __half g_hsh[M_ * D_];   // fp16 hidden_states
__device__ __half g_qh[M_ * D_];    // Q pre-scaled by SC_
__device__ __half g_kh[M_ * D_];
__device__ __half g_vt[M_ * D_];    // V transposed: [b][d_model][s]
__device__ __half g_ch[M_ * D_];    // ctx fp16
__device__ float  g_gate[M_];
__device__ __half g_wqt[D_ * D_];   // fp16, transposed weights [n][k] (Wq pre-scaled)
__device__ __half g_wkt[D_ * D_];
__device__ __half g_wvt[D_ * D_];
__device__ __half g_wot[D_ * D_];

// ============================================================
// helpers
// ============================================================
__device__ __forceinline__ void mma_f16(float4& d, const uint32_t a[4], uint32_t b0, uint32_t b1) {
    asm volatile(
        "mma.sync.aligned.m16n8k16.row.col.f32.f16.f16.f32 "
        "{%0,%1,%2,%3}, {%4,%5,%6,%7}, {%8,%9}, {%0,%1,%2,%3};"
        : "+f"(d.x), "+f"(d.y), "+f"(d.z), "+f"(d.w)
        : "r"(a[0]), "r"(a[1]), "r"(a[2]), "r"(a[3]), "r"(b0), "r"(b1));
}
__device__ __forceinline__ void ldm4(uint32_t& r0, uint32_t& r1, uint32_t& r2, uint32_t& r3,
                                     uint32_t addr) {
    asm volatile("ldmatrix.sync.aligned.m8n8.x4.shared.b16 {%0,%1,%2,%3}, [%4];"
                 : "=r"(r0), "=r"(r1), "=r"(r2), "=r"(r3) : "r"(addr));
}
__device__ __forceinline__ void cp16(uint32_t saddr, const void* gptr) {
    asm volatile("cp.async.cg.shared.global [%0], [%1], 16;" :: "r"(saddr), "l"(gptr));
}
#define CP_COMMIT() asm volatile("cp.async.commit_group;")
#define CP_WAIT0()  asm volatile("cp.async.wait_group 0;")

__device__ __forceinline__ uint32_t f2h2(float a, float b) {
    __half2 h = __floats2half2_rn(a, b);
    return *(uint32_t*)&h;
}
__device__ __forceinline__ uint32_t hmax2u(uint32_t a, uint32_t b) {
    __half2 r = __hmax2(*(__half2*)&a, *(__half2*)&b);
    return *(uint32_t*)&r;
}
__device__ __forceinline__ uint32_t hsub2u(uint32_t a, uint32_t b) {
    __half2 r = __hsub2(*(__half2*)&a, *(__half2*)&b);
    return *(uint32_t*)&r;
}
__device__ __forceinline__ uint32_t ex2u(uint32_t a) {
    uint32_t d;
    asm("ex2.approx.f16x2 %0, %1;" : "=r"(d) : "r"(a));
    return d;
}
#define ONES_H2 0x3C003C00u

// ============================================================
// hs -> fp16 + gating (one pass)
// ============================================================
__global__ __launch_bounds__(256) void hs_pre(const float* __restrict__ hs,
                                              __half* __restrict__ hsh,
                                              const float* __restrict__ gf,
                                              const float* __restrict__ gb,
                                              float* __restrict__ gate)
{
    __shared__ float red[8];
    int row = blockIdx.x;
    int t = threadIdx.x;
    float4 v = *(const float4*)(hs + (size_t)row * D_ + t * 4);
    float s = (v.x + v.y) + (v.z + v.w);
    __half2* dst = (__half2*)(hsh + (size_t)row * D_ + t * 4);
    dst[0] = __floats2half2_rn(v.x, v.y);
    dst[1] = __floats2half2_rn(v.z, v.w);
    #pragma unroll
    for (int st = 16; st > 0; st >>= 1) s += __shfl_xor_sync(0xffffffffu, s, st);
    if ((t & 31) == 0) red[t >> 5] = s;
    __syncthreads();
    if (t == 0) {
        float tot = 0.f;
        #pragma unroll
        for (int i = 0; i < 8; i++) tot += red[i];
        float z = gf[0] * (tot * (1.0f / D_)) + gb[0];
        gate[row] = 1.0f / (1.0f + expf(-z));
    }
}

// ============================================================
// weight transpose + fp16: dst[n][k] = h(scale * src[k][n])
// z=0 (Wq) gets scale SC_ folded in (fp32).
// ============================================================
__global__ __launch_bounds__(256) void wt_pre(const float* __restrict__ w0,
                                              const float* __restrict__ w1,
                                              const float* __restrict__ w2,
                                              const float* __restrict__ w3,
                                              __half* __restrict__ o0,
                                              __half* __restrict__ o1,
                                              __half* __restrict__ o2,
                                              __half* __restrict__ o3)
{
    __shared__ float t[32][33];
    const float* src = (blockIdx.z == 0) ? w0 : (blockIdx.z == 1) ? w1 : (blockIdx.z == 2) ? w2 : w3;
    __half*      dst = (blockIdx.z == 0) ? o0 : (blockIdx.z == 1) ? o1 : (blockIdx.z == 2) ? o2 : o3;
    const float scale = (blockIdx.z == 0) ? SC_ : 1.0f;
    int k0 = blockIdx.y * 32, n0 = blockIdx.x * 32;
    int tx = threadIdx.x & 31, ty = threadIdx.x >> 5;
    #pragma unroll
    for (int r = 0; r < 4; r++)
        t[ty + 8 * r][tx] = src[(size_t)(k0 + ty + 8 * r) * D_ + n0 + tx];
    __syncthreads();
    #pragma unroll
    for (int r = 0; r < 4; r++)
        dst[(size_t)(n0 + ty + 8 * r) * D_ + k0 + tx] = __float2half_rn(scale * t[tx][ty + 8 * r]);
}

// ============================================================
// fp16 GEMM body: C = A @ Wt^T + bscale*bias
// 128x128 tile, BK=64, 256 thr, ldmatrix, cp.async double-buffered,
// ONE syncthreads per k-iter (prefetch issued after the barrier).
// mode: 0=float out, 1=half out, 2=half Vt out.
// ============================================================
#define GLD 72
#define GST (128 * GLD)

__device__ __forceinline__ void gemm_body(const __half* __restrict__ A,
                                          const __half* __restrict__ Wt,
                                          const float* __restrict__ bias,
                                          void* __restrict__ Cout,
                                          int mode, __half* smh,
                                          int m0, int n0, float bscale)
{
    __half* Ast = smh;
    __half* Bst = smh + 2 * GST;
    uint32_t sA = (uint32_t)__cvta_generic_to_shared(Ast);
    uint32_t sB = (uint32_t)__cvta_generic_to_shared(Bst);

    const int tid  = threadIdx.x;
    const int lane = tid & 31;
    const int warp = tid >> 5;
    const int wm = warp & 1;
    const int wn = warp >> 1;
    const int g  = lane >> 2;
    const int t4 = lane & 3;

    const int crow = tid >> 3;
    const int cch  = (tid & 7) * 8;

    float4 acc[4][4];
    #pragma unroll
    for (int mt = 0; mt < 4; mt++)
        #pragma unroll
        for (int nt = 0; nt < 4; nt++)
            acc[mt][nt] = make_float4(0.f, 0.f, 0.f, 0.f);

    // prologue: k-tile 0 -> stage 0
    #pragma unroll
    for (int i = 0; i < 4; i++) {
        int row = crow + i * 32;
        cp16(sA + (row * GLD + cch) * 2, &A[(size_t)(m0 + row) * D_ + cch]);
        cp16(sB + (row * GLD + cch) * 2, &Wt[(size_t)(n0 + row) * D_ + cch]);
    }
    CP_COMMIT();

    const int lrow8 = ((lane >> 3) & 1) * 8 + (lane & 7);
    const int lkhi  = (lane >> 4) * 8;
    const uint32_t aOff = ((wm * 64 + lrow8) * GLD + lkhi) * 2;
    const uint32_t bOff = ((wn * 32 + lrow8) * GLD + lkhi) * 2;

    for (int it = 0; it < 16; it++) {
        const int cur = it & 1;
        CP_WAIT0();              // k-tile 'it' resident
        __syncthreads();         // all warps done with the other stage too
        if (it + 1 < 16) {       // prefetch AFTER barrier -> safe to overwrite
            const int k0 = (it + 1) * 64;
            const int nxt = cur ^ 1;
            #pragma unroll
            for (int i = 0; i < 4; i++) {
                int row = crow + i * 32;
                cp16(sA + (nxt * GST + row * GLD + cch) * 2, &A[(size_t)(m0 + row) * D_ + k0 + cch]);
                cp16(sB + (nxt * GST + row * GLD + cch) * 2, &Wt[(size_t)(n0 + row) * D_ + k0 + cch]);
            }
            CP_COMMIT();
        }

        const uint32_t aB = sA + cur * GST * 2 + aOff;
        const uint32_t bB = sB + cur * GST * 2 + bOff;
        #pragma unroll
        for (int ks = 0; ks < 4; ks++) {
            uint32_t bf[4][2];
            #pragma unroll
            for (int p = 0; p < 2; p++) {
                uint32_t r0, r1, r2, r3;
                ldm4(r0, r1, r2, r3, bB + (p * 16 * GLD + ks * 16) * 2);
                bf[2 * p][0] = r0; bf[2 * p + 1][0] = r1;
                bf[2 * p][1] = r2; bf[2 * p + 1][1] = r3;
            }
            #pragma unroll
            for (int mt = 0; mt < 4; mt++) {
                uint32_t af[4];
                ldm4(af[0], af[1], af[2], af[3], aB + (mt * 16 * GLD + ks * 16) * 2);
                #pragma unroll
                for (int nt = 0; nt < 4; nt++)
                    mma_f16(acc[mt][nt], af, bf[nt][0], bf[nt][1]);
            }
        }
    }

    if (mode == 0) {
        float* C = (float*)Cout;
        #pragma unroll
        for (int nt = 0; nt < 4; nt++) {
            int col = n0 + wn * 32 + nt * 8 + t4 * 2;
            float2 bb = *(const float2*)&bias[col];
            bb.x *= bscale; bb.y *= bscale;
            #pragma unroll
            for (int mt = 0; mt < 4; mt++) {
                int row = m0 + wm * 64 + mt * 16 + g;
                float2 o;
                o.x = acc[mt][nt].x + bb.x; o.y = acc[mt][nt].y + bb.y;
                *(float2*)&C[(size_t)row * D_ + col] = o;
                o.x = acc[mt][nt].z + bb.x; o.y = acc[mt][nt].w + bb.y;
                *(float2*)&C[(size_t)(row + 8) * D_ + col] = o;
            }
        }
    } else if (mode == 1) {
        __half* C = (__half*)Cout;
        #pragma unroll
        for (int nt = 0; nt < 4; nt++) {
            int col = n0 + wn * 32 + nt * 8 + t4 * 2;
            float2 bb = *(const float2*)&bias[col];
            bb.x *= bscale; bb.y *= bscale;
            #pragma unroll
            for (int mt = 0; mt < 4; mt++) {
                int row = m0 + wm * 64 + mt * 16 + g;
                *(__half2*)&C[(size_t)row * D_ + col] =
                    __floats2half2_rn(acc[mt][nt].x + bb.x, acc[mt][nt].y + bb.y);
                *(__half2*)&C[(size_t)(row + 8) * D_ + col] =
                    __floats2half2_rn(acc[mt][nt].z + bb.x, acc[mt][nt].w + bb.y);
            }
        }
    } else {
        __syncthreads();
        __half* T = smh;   // [128 cols][144 rows pad]
        #pragma unroll
        for (int nt = 0; nt < 4; nt++) {
            int col = wn * 32 + nt * 8 + 2 * t4;
            float2 bb = *(const float2*)&bias[n0 + col];
            #pragma unroll
            for (int mt = 0; mt < 4; mt++) {
                int row = wm * 64 + mt * 16 + g;
                T[col * 144 + row]           = __float2half_rn(acc[mt][nt].x + bb.x);
                T[(col + 1) * 144 + row]     = __float2half_rn(acc[mt][nt].y + bb.y);
                T[col * 144 + row + 8]       = __float2half_rn(acc[mt][nt].z + bb.x);
                T[(col + 1) * 144 + row + 8] = __float2half_rn(acc[mt][nt].w + bb.y);
            }
        }
        __syncthreads();
        __half* Vt = (__half*)Cout;
        int colc  = tid >> 1;
        int roff  = (tid & 1) * 64;
        int bb2   = m0 >> 11;
        int ms    = (m0 & (S_ - 1)) + roff;
        const uint4* src = (const uint4*)&T[colc * 144 + roff];
        uint4* dst = (uint4*)(Vt + ((size_t)bb2 * D_ + n0 + colc) * S_ + ms);
        #pragma unroll
        for (int i = 0; i < 8; i++) dst[i] = src[i];
    }
}

__global__ __launch_bounds__(256) void gemm_qkv(const __half* __restrict__ A,
                                                const float* __restrict__ bq,
                                                const float* __restrict__ bk,
                                                const float* __restrict__ bv)
{
    extern __shared__ __half smh[];
    const int m0 = blockIdx.y * 128;
    const int n0 = blockIdx.x * 128;
    if (blockIdx.z == 0)      gemm_body(A, g_wqt, bq, g_qh, 1, smh, m0, n0, SC_);
    else if (blockIdx.z == 1) gemm_body(A, g_wkt, bk, g_kh, 1, smh, m0, n0, 1.0f);
    else                      gemm_body(A, g_wvt, bv, g_vt, 2, smh, m0, n0, 1.0f);
}

__global__ __launch_bounds__(256) void gemm_o(const __half* __restrict__ A,
                                              const float* __restrict__ bo,
                                              float* __restrict__ out)
{
    extern __shared__ __half smh[];
    gemm_body(A, g_wot, bo, out, 0, smh, blockIdx.y * 128, blockIdx.x * 128, 1.0f);
}

// ============================================================
// fp16 flash attention: fp16 softmax, ones-MMA rowsums,
// ONE syncthreads per chunk, corr==1 fast path (bit-exact skip).
// Block = 128 thr (4 warps) = 64-query tile of one (b,h).
// dyn smem: 4 * 64*72 halves = 36864 B
// ============================================================
#define AH_ST (64 * 72)

__global__ __launch_bounds__(128) void attn_h(const __half* __restrict__ q,
                                              const __half* __restrict__ k,
                                              const __half* __restrict__ vt,
                                              const float* __restrict__ gate,
                                              __half* __restrict__ ctx)
{
    extern __shared__ __half smh[];
    __half* Kst = smh;
    __half* Vst = smh + 2 * AH_ST;
    uint32_t sK = (uint32_t)__cvta_generic_to_shared(Kst);
    uint32_t sV = (uint32_t)__cvta_generic_to_shared(Vst);

    const int b  = blockIdx.z;
    const int h  = blockIdx.y;
    const int q0 = blockIdx.x * 64;
    const int tid  = threadIdx.x;
    const int lane = tid & 31;
    const int w    = tid >> 5;
    const int g  = lane >> 2;
    const int t4 = lane & 3;
    const int wrow = w * 16;

    // ---- stage Q tile through Kst stage0, pull fragments ----
    #pragma unroll
    for (int i = 0; i < 4; i++) {
        int e = tid + i * 128;
        int row = e >> 3, ch = (e & 7) * 8;
        *(uint4*)&Kst[row * 72 + ch] =
            *(const uint4*)(q + ((size_t)(b * S_ + q0 + row)) * D_ + h * DH_ + ch);
    }
    __syncthreads();
    uint32_t aq[4][4];
    {
        const int lr = ((lane >> 3) & 1) * 8 + (lane & 7);
        const int lk = (lane >> 4) * 8;
        uint32_t qB = sK + ((wrow + lr) * 72 + lk) * 2;
        #pragma unroll
        for (int ks = 0; ks < 4; ks++)
            ldm4(aq[ks][0], aq[ks][1], aq[ks][2], aq[ks][3], qB + ks * 32);
    }
    __syncthreads();

    float4 accO[8];
    #pragma unroll
    for (int nt = 0; nt < 8; nt++) accO[nt] = make_float4(0.f, 0.f, 0.f, 0.f);
    float llo = 0.f, lhi = 0.f;
    uint32_t mx2 = f2h2(-30000.f, -30000.f);

    const int crow = tid >> 3;
    const int cch  = (tid & 7) * 8;

    const __half* kbase  = k  + ((size_t)b * S_) * D_ + h * DH_;
    const __half* vtbase = vt + ((size_t)b * D_ + h * DH_) * S_;

    // prologue: chunk 0 -> stage 0
    #pragma unroll
    for (int i = 0; i < 4; i++) {
        int row = crow + i * 16;
        cp16(sK + (row * 72 + cch) * 2, kbase + (size_t)row * D_ + cch);
        cp16(sV + (row * 72 + cch) * 2, vtbase + (size_t)row * S_ + cch);
    }
    CP_COMMIT();

    const int lrow8 = ((lane >> 3) & 1) * 8 + (lane & 7);
    const int lkhi  = (lane >> 4) * 8;
    const uint32_t fOff = (lrow8 * 72 + lkhi) * 2;

    for (int c = 0; c < S_ / 64; c++) {
        const int cur = c & 1;
        CP_WAIT0();              // chunk c resident
        __syncthreads();         // all warps done reading the other stage
        if (c + 1 < S_ / 64) {   // prefetch AFTER barrier
            const int kc = (c + 1) * 64;
            const int nxt = cur ^ 1;
            #pragma unroll
            for (int i = 0; i < 4; i++) {
                int row = crow + i * 16;
                cp16(sK + (nxt * AH_ST + row * 72 + cch) * 2, kbase + (size_t)(kc + row) * D_ + cch);
                cp16(sV + (nxt * AH_ST + row * 72 + cch) * 2, vtbase + (size_t)row * S_ + kc + cch);
            }
            CP_COMMIT();
        }

        const uint32_t kB = sK + cur * AH_ST * 2 + fOff;
        const uint32_t vB = sV + cur * AH_ST * 2 + fOff;

        // ---- scores = Q @ K^T (pre-scaled: log2-domain) ----
        float4 s[8];
        #pragma unroll
        for (int nt = 0; nt < 8; nt++) s[nt] = make_float4(0.f, 0.f, 0.f, 0.f);
        #pragma unroll
        for (int ks = 0; ks < 4; ks++) {
            #pragma unroll
            for (int p = 0; p < 4; p++) {
                uint32_t r0, r1, r2, r3;
                ldm4(r0, r1, r2, r3, kB + (p * 16 * 72 + ks * 16) * 2);
                mma_f16(s[2 * p],     aq[ks], r0, r2);
                mma_f16(s[2 * p + 1], aq[ks], r1, r3);
            }
        }

        // ---- fp16 softmax ----
        uint32_t pl[8], ph[8];
        #pragma unroll
        for (int nt = 0; nt < 8; nt++) {
            pl[nt] = f2h2(s[nt].x, s[nt].y);   // row g
            ph[nt] = f2h2(s[nt].z, s[nt].w);   // row g+8
        }
        uint32_t mgu = pl[0], mhu = ph[0];
        #pragma unroll
        for (int nt = 1; nt < 8; nt++) { mgu = hmax2u(mgu, pl[nt]); mhu = hmax2u(mhu, ph[nt]); }
        __half2 mgh = *(__half2*)&mgu;
        __half2 mhh = *(__half2*)&mhu;
        __half2 mc = __halves2half2(__hmax(__low2half(mgh), __high2half(mgh)),
                                    __hmax(__low2half(mhh), __high2half(mhh)));
        uint32_t mcu = *(uint32_t*)&mc;
        mcu = hmax2u(mcu, __shfl_xor_sync(0xffffffffu, mcu, 1));
        mcu = hmax2u(mcu, __shfl_xor_sync(0xffffffffu, mcu, 2));
        uint32_t mn2 = hmax2u(mcu, mx2);

        // corr==1 fast path: if no row max in this warp changed, skip rescale
        float clo = 1.f, chi = 1.f;
        bool allsame = __all_sync(0xffffffffu, mn2 == mx2);
        if (!allsame) {
            uint32_t corr2 = ex2u(hsub2u(mx2, mn2));
            __half2 c2 = *(__half2*)&corr2;
            clo = __low2float(c2);
            chi = __high2float(c2);
            #pragma unroll
            for (int nt = 0; nt < 8; nt++) {
                accO[nt].x *= clo; accO[nt].y *= clo;
                accO[nt].z *= chi; accO[nt].w *= chi;
            }
        }
        mx2 = mn2;

        __half2 mn2h = *(__half2*)&mn2;
        __half2 bg = __half2half2(__low2half(mn2h));
        __half2 bh = __half2half2(__high2half(mn2h));
        uint32_t bgu = *(uint32_t*)&bg;
        uint32_t bhu = *(uint32_t*)&bh;
        #pragma unroll
        for (int nt = 0; nt < 8; nt++) {
            pl[nt] = ex2u(hsub2u(pl[nt], bgu));
            ph[nt] = ex2u(hsub2u(ph[nt], bhu));
        }

        // ---- row sums via ones-MMA ----
        float4 accS = make_float4(0.f, 0.f, 0.f, 0.f);
        #pragma unroll
        for (int ks = 0; ks < 4; ks++) {
            uint32_t ap[4] = {pl[2 * ks], ph[2 * ks], pl[2 * ks + 1], ph[2 * ks + 1]};
            mma_f16(accS, ap, ONES_H2, ONES_H2);
        }
        llo = llo * clo + accS.x;
        lhi = lhi * chi + accS.z;

        // ---- O += P @ V ----
        #pragma unroll
        for (int ks = 0; ks < 4; ks++) {
            uint32_t ap[4] = {pl[2 * ks], ph[2 * ks], pl[2 * ks + 1], ph[2 * ks + 1]};
            #pragma unroll
            for (int p = 0; p < 4; p++) {
                uint32_t r0, r1, r2, r3;
                ldm4(r0, r1, r2, r3, vB + (p * 16 * 72 + ks * 16) * 2);
                mma_f16(accO[2 * p],     ap, r0, r2);
                mma_f16(accO[2 * p + 1], ap, r1, r3);
            }
        }
    }

    // ---- epilogue: gate/l scale, fp16 store ----
    int qlo = q0 + wrow + g;
    int qhi = qlo + 8;
    float glo = gate[b * S_ + qlo] / llo;
    float ghi = gate[b * S_ + qhi] / lhi;
    #pragma unroll
    for (int nt = 0; nt < 8; nt++) {
        int col = h * DH_ + nt * 8 + 2 * t4;
        *(__half2*)&ctx[((size_t)(b * S_ + qlo)) * D_ + col] =
            __floats2half2_rn(accO[nt].x * glo, accO[nt].y * glo);
        *(__half2*)&ctx[((size_t)(b * S_ + qhi)) * D_ + col] =
            __floats2half2_rn(accO[nt].z * ghi, accO[nt].w * ghi);
    }
}

// ============================================================
// Launch
// ============================================================
extern "C" void kernel_launch(void* const* d_in, const int* in_sizes, int n_in,
                              void* d_out, int out_size)
{
    const float* hs = (const float*)d_in[0];
    const float* Wq = (const float*)d_in[1];
    const float* bq = (const float*)d_in[2];
    const float* Wk = (const float*)d_in[3];
    const float* bk = (const float*)d_in[4];
    const float* Wv = (const float*)d_in[5];
    const float* bv = (const float*)d_in[6];
    const float* Wo = (const float*)d_in[7];
    const float* bo = (const float*)d_in[8];
    const float* gf = (const float*)d_in[9];
    const float* gb = (const float*)d_in[10];
    float* out = (float*)d_out;

    __half *hsh, *qh, *kh, *vtp, *ch;
    float *gp;
    cudaGetSymbolAddress((void**)&hsh, g_hsh);
    cudaGetSymbolAddress((void**)&qh, g_qh);
    cudaGetSymbolAddress((void**)&kh, g_kh);
    cudaGetSymbolAddress((void**)&vtp, g_vt);
    cudaGetSymbolAddress((void**)&ch, g_ch);
    cudaGetSymbolAddress((void**)&gp, g_gate);
    __half *wq, *wk, *wv, *wo;
    cudaGetSymbolAddress((void**)&wq, g_wqt);
    cudaGetSymbolAddress((void**)&wk, g_wkt);
    cudaGetSymbolAddress((void**)&wv, g_wvt);
    cudaGetSymbolAddress((void**)&wo, g_wot);

    const int SMEM_G = 73728;
    const int SMEM_A = 36864;
    cudaFuncSetAttribute(gemm_qkv, cudaFuncAttributeMaxDynamicSharedMemorySize, SMEM_G);
    cudaFuncSetAttribute(gemm_o,   cudaFuncAttributeMaxDynamicSharedMemorySize, SMEM_G);
    cudaFuncSetAttribute(attn_h,   cudaFuncAttributeMaxDynamicSharedMemorySize, SMEM_A);

    hs_pre<<<M_, 256>>>(hs, hsh, gf, gb, gp);
    wt_pre<<<dim3(32, 32, 4), 256>>>(Wq, Wk, Wv, Wo, wq, wk, wv, wo);

    gemm_qkv<<<dim3(D_ / 128, M_ / 128, 3), 256, SMEM_G>>>(hsh, bq, bk, bv);
    attn_h<<<dim3(S_ / 64, H_, B_), 128, SMEM_A>>>(qh, kh, vtp, gp, ch);
    gemm_o<<<dim3(D_ / 128, M_ / 128), 256, SMEM_G>>>(ch, bo, out);
}